// round 8
// baseline (speedup 1.0000x reference)
#include <cuda_runtime.h>
#include <cuda_fp16.h>
#include <cstdint>

#define NB 64
#define NS 512
#define NTA 8
#define ND 768

// ------------------------------------------------------------------
// scratch (static __device__; no allocations allowed)
// ------------------------------------------------------------------
__device__ float g_mlen[NB], g_alen[NB];
__device__ float g_vs[NB * ND];          // [b][d] (for soft_vts)
__device__ float g_vat[ND * NB];         // transposed [k][b]
__device__ float g_vst[ND * NB];         // transposed [k][b]
__device__ float g_ctx[NB * ND];
__device__ float g_scores[NB * NS];
__device__ float g_vnst[ND * NB];        // transposed [k][b]
__device__ float g_vms[NB * ND];

// fp16 operands
__device__ __half g_Ah[(size_t)NB * NS * ND];
__device__ __half g_Bh[(size_t)ND * ND];   // [n][k] = W1_m[k][n]

// ------------------------------------------------------------------
// PTX helpers (baseline ISA only)
// ------------------------------------------------------------------
__device__ __forceinline__ uint32_t smem_u32(const void* p) {
    uint32_t a;
    asm("{ .reg .u64 t; cvta.to.shared.u64 t, %1; cvt.u32.u64 %0, t; }" : "=r"(a) : "l"(p));
    return a;
}
__device__ __forceinline__ void cp16(uint32_t dst, const void* src) {
    asm volatile("cp.async.cg.shared.global [%0], [%1], 16;" :: "r"(dst), "l"(src));
}
#define CP_COMMIT() asm volatile("cp.async.commit_group;" ::: "memory")
#define CP_WAIT1()  asm volatile("cp.async.wait_group 1;" ::: "memory")
#define CP_WAIT0()  asm volatile("cp.async.wait_group 0;" ::: "memory")

__device__ __forceinline__ void ldsm4(uint32_t& r0, uint32_t& r1, uint32_t& r2, uint32_t& r3,
                                      uint32_t addr) {
    asm volatile("ldmatrix.sync.aligned.m8n8.x4.shared.b16 {%0,%1,%2,%3}, [%4];"
                 : "=r"(r0), "=r"(r1), "=r"(r2), "=r"(r3) : "r"(addr));
}
__device__ __forceinline__ void mma16816(float* c, uint32_t a0, uint32_t a1, uint32_t a2,
                                         uint32_t a3, uint32_t b0, uint32_t b1) {
    asm volatile(
        "mma.sync.aligned.m16n8k16.row.col.f32.f16.f16.f32 "
        "{%0,%1,%2,%3}, {%4,%5,%6,%7}, {%8,%9}, {%0,%1,%2,%3};"
        : "+f"(c[0]), "+f"(c[1]), "+f"(c[2]), "+f"(c[3])
        : "r"(a0), "r"(a1), "r"(a2), "r"(a3), "r"(b0), "r"(b1));
}
__device__ __forceinline__ uint32_t tanh2_f16(uint32_t x) {
    uint32_t y;
    asm("tanh.approx.f16x2 %0, %1;" : "=r"(y) : "r"(x));
    return y;
}

// ------------------------------------------------------------------
// fused init: blocks [0,NB) = lengths; blocks [NB, NB+576) = W1_m transpose
// ------------------------------------------------------------------
__global__ __launch_bounds__(256) void k_init(const int* __restrict__ ids,
                                              const int* __restrict__ tids,
                                              const float* __restrict__ W1) {
    if (blockIdx.x < NB) {
        int b = blockIdx.x;
        __shared__ int sm[256];
        int tid = threadIdx.x;
        int c = 0;
        for (int s = tid; s < NS; s += 256) c += (ids[b * NS + s] != 0);
        sm[tid] = c;
        __syncthreads();
        for (int o = 128; o > 0; o >>= 1) {
            if (tid < o) sm[tid] += sm[tid + o];
            __syncthreads();
        }
        if (tid == 0) {
            g_mlen[b] = fmaxf((float)sm[0], 1.0f);
            int a = 0;
            for (int t = 0; t < NTA; t++) a += (tids[b * NTA + t] != 0);
            g_alen[b] = fmaxf((float)a, 1.0f);
        }
    } else {
        __shared__ float t[32][33];
        int blk = blockIdx.x - NB;            // 0..575 = 24x24
        int k0 = (blk % 24) * 32, n0 = (blk / 24) * 32;
        int tx = threadIdx.x & 31, ty = threadIdx.x >> 5;   // 32 x 8
        for (int i = ty; i < 32; i += 8)
            t[i][tx] = W1[(size_t)(k0 + i) * ND + n0 + tx];
        __syncthreads();
        for (int i = ty; i < 32; i += 8)
            g_Bh[(size_t)(n0 + i) * ND + k0 + tx] = __float2half_rn(t[tx][i]);
    }
}

// ------------------------------------------------------------------
// means + fp16 convert (float2 per thread), transposed v outputs
// ------------------------------------------------------------------
__global__ __launch_bounds__(512) void k_means(const float* __restrict__ mem,
                                               const float* __restrict__ asp) {
    __shared__ float sp[4][256];
    int b = blockIdx.y;
    int tid = threadIdx.x;
    int dp = tid & 127;                // 128 d-pairs
    int d = blockIdx.x * 256 + dp * 2;
    int q = tid >> 7;
    float2 acc = make_float2(0.f, 0.f);
    const float* p = mem + ((size_t)b * NS + q * 128) * ND + d;
    __half2* ah = (__half2*)(g_Ah + ((size_t)b * NS + q * 128) * ND + d);
#pragma unroll 8
    for (int s = 0; s < 128; s++) {
        float2 v = *(const float2*)(p + (size_t)s * ND);
        acc.x += v.x; acc.y += v.y;
        ah[(size_t)s * (ND / 2)] = __floats2half2_rn(v.x, v.y);
    }
    sp[q][dp * 2] = acc.x;
    sp[q][dp * 2 + 1] = acc.y;
    __syncthreads();
    if (q < 2) {
        int dd = d + q;                // two threads handle the pair
        int i = dp * 2 + q;
        float tot = sp[0][i] + sp[1][i] + sp[2][i] + sp[3][i];
        float vs = tot / g_mlen[b];
        g_vs[b * ND + dd] = vs;
        g_vst[dd * NB + b] = vs;
        float a = 0.f;
        const float* ap = asp + ((size_t)b * NTA) * ND + dd;
#pragma unroll
        for (int t = 0; t < NTA; t++) a += ap[(size_t)t * ND];
        g_vat[dd * NB + b] = a / g_alen[b];
    }
}

// ------------------------------------------------------------------
// ctx = v_a @ W1_a + v_s @ W1_s + b1   (b-tiled x8, transposed v)
// grid (ND/128, NB/8), 512 thr = 128 d x 4 q (2 mats x 2 k-halves)
// ------------------------------------------------------------------
__global__ __launch_bounds__(512) void k_ctx(const float* __restrict__ W1,
                                             const float* __restrict__ b1) {
    __shared__ float sp[4][128][8];
    int tid = threadIdx.x;
    int dt = tid & 127;
    int d = blockIdx.x * 128 + dt;
    int q = tid >> 7;
    int b0 = blockIdx.y * 8;
    const float* W = W1 + (size_t)(1 + (q >> 1)) * ND * ND + d;
    const float* vt = ((q >> 1) ? g_vst : g_vat) + b0;
    int k0 = (q & 1) * 384;
    float acc[8];
#pragma unroll
    for (int i = 0; i < 8; i++) acc[i] = 0.f;
#pragma unroll 4
    for (int k = 0; k < 384; k++) {
        float w = W[(size_t)(k0 + k) * ND];
        float4 v0 = *(const float4*)(vt + (k0 + k) * NB);
        float4 v1 = *(const float4*)(vt + (k0 + k) * NB + 4);
        acc[0] = fmaf(v0.x, w, acc[0]); acc[1] = fmaf(v0.y, w, acc[1]);
        acc[2] = fmaf(v0.z, w, acc[2]); acc[3] = fmaf(v0.w, w, acc[3]);
        acc[4] = fmaf(v1.x, w, acc[4]); acc[5] = fmaf(v1.y, w, acc[5]);
        acc[6] = fmaf(v1.z, w, acc[6]); acc[7] = fmaf(v1.w, w, acc[7]);
    }
#pragma unroll
    for (int i = 0; i < 8; i++) sp[q][dt][i] = acc[i];
    __syncthreads();
    if (q == 0) {
        float bb = b1[d];
#pragma unroll
        for (int i = 0; i < 8; i++) {
            float s = sp[0][dt][i] + sp[1][dt][i] + sp[2][dt][i] + sp[3][dt][i] + bb;
            g_ctx[(b0 + i) * ND + d] = s;
        }
    }
}

// ------------------------------------------------------------------
// fused scores: mma.sync fp16 GEMM + tanh/w2 epilogue
// ------------------------------------------------------------------
#define MT 128
#define NTILE 128
#define KC 64
#define NCHUNKS (ND / NTILE)   // 6
#define KSTEPS (ND / KC)       // 12
#define APAD 144

#define OFF_A 0
#define OFF_B 18432
#define BUFSZ 36864
#define OFF_CTX (2 * BUFSZ)
#define OFF_W2  (OFF_CTX + 3072)
#define OFF_RED (OFF_W2 + 3072)
#define SMEMSZ  (OFF_RED + 1024)

struct ScoreCtx {
    const __half* gA;
    uint32_t sbase;
};

__device__ __forceinline__ void stage_tiles(const ScoreCtx& sc, int nbase, int k0, int buf) {
    int tid = threadIdx.x;
    uint32_t sb = sc.sbase + buf * BUFSZ;
#pragma unroll
    for (int t = 0; t < 4; t++) {
        int i = tid + t * 256;
        int r = i >> 3, c = i & 7;
        uint32_t d = sb + r * APAD + c * 16;
        cp16(d + OFF_A, sc.gA + (size_t)r * ND + k0 + c * 8);
        cp16(d + OFF_B, g_Bh + (size_t)(nbase + r) * ND + k0 + c * 8);
    }
}

__global__ void __launch_bounds__(256, 2) k_scores(const float* __restrict__ w2) {
    extern __shared__ char smem[];
    const int tid = threadIdx.x;
    const int b = blockIdx.y;
    const int s0 = blockIdx.x * MT;
    const int lane = tid & 31, wid = tid >> 5;
    const int warp_m = wid & 3, warp_n = wid >> 2;

    float* sctx = (float*)(smem + OFF_CTX);
    float* sw2p = (float*)(smem + OFF_W2);
    for (int i = tid; i < ND; i += 256) {
        sctx[i] = g_ctx[b * ND + i];
        sw2p[i] = w2[i];
    }

    ScoreCtx sc;
    sc.gA = g_Ah + ((size_t)b * NS + s0) * ND;
    sc.sbase = smem_u32(smem);

    const float mlen = g_mlen[b];
    float loc[2][2], rowsum[2][2];
#pragma unroll
    for (int mt = 0; mt < 2; mt++)
#pragma unroll
        for (int h = 0; h < 2; h++) {
            float srow = (float)(s0 + warp_m * 32 + mt * 16 + h * 8 + (lane >> 2));
            loc[mt][h] = (srow < mlen) ? (1.0f - srow / mlen) : 1.0f;
            rowsum[mt][h] = 0.f;
        }

    const int a_row = warp_m * 32 + (lane & 7) + ((lane >> 3) & 1) * 8;
    const int a_halfoff = (lane >> 4) * 16;
    const int b_row = warp_n * 64 + (lane & 7) + (lane >> 4) * 8;
    const int b_halfoff = ((lane >> 3) & 1) * 16;

    __syncthreads();

    stage_tiles(sc, 0, 0, 0);
    CP_COMMIT();

    for (int chunk = 0; chunk < NCHUNKS; chunk++) {
        const int nbase = chunk * NTILE;
        float acc[2][8][4];
#pragma unroll
        for (int mt = 0; mt < 2; mt++)
#pragma unroll
            for (int nt = 0; nt < 8; nt++)
#pragma unroll
                for (int j = 0; j < 4; j++) acc[mt][nt][j] = 0.f;

        for (int ks = 0; ks < KSTEPS; ks++) {
            const int buf = ks & 1;
            if (ks + 1 < KSTEPS) {
                stage_tiles(sc, nbase, (ks + 1) * KC, buf ^ 1);
                CP_COMMIT();
                CP_WAIT1();
            } else {
                CP_WAIT0();
            }
            __syncthreads();

            const uint32_t sb = sc.sbase + buf * BUFSZ;
#pragma unroll
            for (int kk = 0; kk < 4; kk++) {
                const int kb = kk * 32;
                uint32_t ar[2][4], br[4][4];
#pragma unroll
                for (int mt = 0; mt < 2; mt++)
                    ldsm4(ar[mt][0], ar[mt][1], ar[mt][2], ar[mt][3],
                          sb + OFF_A + (a_row + mt * 16) * APAD + kb + a_halfoff);
#pragma unroll
                for (int nt2 = 0; nt2 < 4; nt2++)
                    ldsm4(br[nt2][0], br[nt2][1], br[nt2][2], br[nt2][3],
                          sb + OFF_B + (b_row + nt2 * 16) * APAD + kb + b_halfoff);
#pragma unroll
                for (int mt = 0; mt < 2; mt++)
#pragma unroll
                    for (int nt2 = 0; nt2 < 4; nt2++)
#pragma unroll
                        for (int s = 0; s < 2; s++)
                            mma16816(acc[mt][nt2 * 2 + s], ar[mt][0], ar[mt][1], ar[mt][2],
                                     ar[mt][3], br[nt2][2 * s], br[nt2][2 * s + 1]);
            }
            __syncthreads();
        }

        if (chunk + 1 < NCHUNKS) {
            stage_tiles(sc, nbase + NTILE, 0, 0);
            CP_COMMIT();
        }

#pragma unroll
        for (int mt = 0; mt < 2; mt++) {
#pragma unroll
            for (int nt = 0; nt < 8; nt++) {
                const int c0 = nbase + warp_n * 64 + nt * 8 + (lane & 3) * 2;
                const float2 cx = *(const float2*)&sctx[c0];
                const float2 wv = *(const float2*)&sw2p[c0];
                {
                    float u0 = fmaf(loc[mt][0], acc[mt][nt][0], cx.x);
                    float u1 = fmaf(loc[mt][0], acc[mt][nt][1], cx.y);
                    __half2 hp = __floats2half2_rn(u0, u1);
                    uint32_t th = tanh2_f16(*(uint32_t*)&hp);
                    float2 tf = __half22float2(*(__half2*)&th);
                    rowsum[mt][0] = fmaf(tf.x, wv.x, fmaf(tf.y, wv.y, rowsum[mt][0]));
                }
                {
                    float u2 = fmaf(loc[mt][1], acc[mt][nt][2], cx.x);
                    float u3 = fmaf(loc[mt][1], acc[mt][nt][3], cx.y);
                    __half2 hp = __floats2half2_rn(u2, u3);
                    uint32_t th = tanh2_f16(*(uint32_t*)&hp);
                    float2 tf = __half22float2(*(__half2*)&th);
                    rowsum[mt][1] = fmaf(tf.x, wv.x, fmaf(tf.y, wv.y, rowsum[mt][1]));
                }
            }
        }
    }

    float* red = (float*)(smem + OFF_RED);
#pragma unroll
    for (int mt = 0; mt < 2; mt++)
#pragma unroll
        for (int h = 0; h < 2; h++) {
            float v = rowsum[mt][h];
            v += __shfl_xor_sync(0xffffffffu, v, 1);
            v += __shfl_xor_sync(0xffffffffu, v, 2);
            if ((lane & 3) == 0) {
                int lrow = warp_m * 32 + mt * 16 + h * 8 + (lane >> 2);
                red[lrow * 2 + warp_n] = v;
            }
        }
    __syncthreads();
    if (tid < MT)
        g_scores[b * NS + s0 + tid] = red[tid * 2] + red[tid * 2 + 1];
}

// ------------------------------------------------------------------
// softmax + v_ts + v_ns (transposed output)
// ------------------------------------------------------------------
__global__ __launch_bounds__(512) void k_soft_vts() {
    int b = blockIdx.x;
    int tid = threadIdx.x;
    __shared__ float sw[NS];
    __shared__ float red[512];
    __shared__ float sp[2][192][4];
    float mlen = g_mlen[b];

    float v = g_scores[b * NS + tid];
    red[tid] = v;
    __syncthreads();
    for (int o = 256; o > 0; o >>= 1) {
        if (tid < o) red[tid] = fmaxf(red[tid], red[tid + o]);
        __syncthreads();
    }
    float m = red[0];
    __syncthreads();
    float e = expf(v - m);
    red[tid] = e;
    __syncthreads();
    for (int o = 256; o > 0; o >>= 1) {
        if (tid < o) red[tid] += red[tid + o];
        __syncthreads();
    }
    float inv = 1.0f / red[0];
    __syncthreads();
    float s = (float)tid;
    float l = (s < mlen) ? (1.0f - s / mlen) : 1.0f;
    sw[tid] = e * inv * l;
    __syncthreads();

    if (tid < 384) {
        int sq = tid / 192;          // 2 s-halves
        int dd = tid % 192;          // 192 groups of 4 d
        int d = dd * 4;
        const __half* p = g_Ah + ((size_t)b * NS + sq * 256) * ND + d;
        float a0 = 0.f, a1 = 0.f, a2 = 0.f, a3 = 0.f;
#pragma unroll 8
        for (int s2 = 0; s2 < 256; s2++) {
            uint2 raw = *(const uint2*)(p + (size_t)s2 * ND);
            float2 h0 = __half22float2(*(__half2*)&raw.x);
            float2 h1 = __half22float2(*(__half2*)&raw.y);
            float w = sw[sq * 256 + s2];
            a0 = fmaf(w, h0.x, a0); a1 = fmaf(w, h0.y, a1);
            a2 = fmaf(w, h1.x, a2); a3 = fmaf(w, h1.y, a3);
        }
        sp[sq][dd][0] = a0; sp[sq][dd][1] = a1;
        sp[sq][dd][2] = a2; sp[sq][dd][3] = a3;
    }
    __syncthreads();
    if (tid < 192) {
        int d = tid * 4;
#pragma unroll
        for (int j = 0; j < 4; j++) {
            float t = sp[0][tid][j] + sp[1][tid][j] + g_vs[b * ND + d + j];
            g_vnst[(d + j) * NB + b] = t;
        }
    }
}

// ------------------------------------------------------------------
// v_ms = tanh(v_ns @ Wm + bm)   (b-tiled x8, transposed v_ns)
// grid (ND/128, NB/8), 512 thr = 128 d x 4 k-quarters
// ------------------------------------------------------------------
__global__ __launch_bounds__(512) void k_vms(const float* __restrict__ Wm,
                                             const float* __restrict__ bm) {
    __shared__ float sp[4][128][8];
    int tid = threadIdx.x;
    int dt = tid & 127;
    int d = blockIdx.x * 128 + dt;
    int q = tid >> 7;
    int b0 = blockIdx.y * 8;
    int k0 = q * 192;
    float acc[8];
#pragma unroll
    for (int i = 0; i < 8; i++) acc[i] = 0.f;
#pragma unroll 4
    for (int k = 0; k < 192; k++) {
        float w = Wm[(size_t)(k0 + k) * ND + d];
        float4 v0 = *(const float4*)(g_vnst + (k0 + k) * NB + b0);
        float4 v1 = *(const float4*)(g_vnst + (k0 + k) * NB + b0 + 4);
        acc[0] = fmaf(v0.x, w, acc[0]); acc[1] = fmaf(v0.y, w, acc[1]);
        acc[2] = fmaf(v0.z, w, acc[2]); acc[3] = fmaf(v0.w, w, acc[3]);
        acc[4] = fmaf(v1.x, w, acc[4]); acc[5] = fmaf(v1.y, w, acc[5]);
        acc[6] = fmaf(v1.z, w, acc[6]); acc[7] = fmaf(v1.w, w, acc[7]);
    }
#pragma unroll
    for (int i = 0; i < 8; i++) sp[q][dt][i] = acc[i];
    __syncthreads();
    if (q == 0) {
        float bb = bm[d];
#pragma unroll
        for (int i = 0; i < 8; i++) {
            float s = sp[0][dt][i] + sp[1][dt][i] + sp[2][dt][i] + sp[3][dt][i] + bb;
            g_vms[(b0 + i) * ND + d] = tanhf(s);
        }
    }
}

// ------------------------------------------------------------------
// logits
// ------------------------------------------------------------------
__global__ void k_logits(const float* __restrict__ Wd,
                         const float* __restrict__ bd,
                         float* __restrict__ out) {
    int t = threadIdx.x;
    if (t >= NB * 3) return;
    int b = t / 3, j = t % 3;
    float acc = bd[j];
    const float* v = g_vms + b * ND;
#pragma unroll 4
    for (int d = 0; d < ND; d++) acc = fmaf(v[d], Wd[d * 3 + j], acc);
    out[b * 3 + j] = acc;
}

// ------------------------------------------------------------------
// launch
// ------------------------------------------------------------------
extern "C" void kernel_launch(void* const* d_in, const int* in_sizes, int n_in,
                              void* d_out, int out_size) {
    (void)in_sizes; (void)n_in; (void)out_size;
    const float* mem  = (const float*)d_in[0];
    const float* asp  = (const float*)d_in[1];
    const int* ids    = (const int*)d_in[2];
    const int* tids   = (const int*)d_in[3];
    const float* W1 = (const float*)d_in[4];
    const float* b1 = (const float*)d_in[5];
    const float* w2 = (const float*)d_in[6];
    const float* Wm = (const float*)d_in[7];
    const float* bm = (const float*)d_in[8];
    const float* Wd = (const float*)d_in[9];
    const float* bd = (const float*)d_in[10];
    float* out = (float*)d_out;

    cudaFuncSetAttribute(k_scores, cudaFuncAttributeMaxDynamicSharedMemorySize, SMEMSZ);

    k_init<<<NB + 576, 256>>>(ids, tids, W1);
    k_means<<<dim3(ND / 256, NB), 512>>>(mem, asp);
    k_ctx<<<dim3(ND / 128, NB / 8), 512>>>(W1, b1);
    k_scores<<<dim3(NS / MT, NB), 256, SMEMSZ>>>(w2);     // 4th launch -> ncu capture
    k_soft_vts<<<NB, 512>>>();
    k_vms<<<dim3(ND / 128, NB / 8), 512>>>(Wm, bm);
    k_logits<<<1, 256>>>(Wd, bd, out);
}

// round 9
// speedup vs baseline: 1.1519x; 1.1519x over previous
#include <cuda_runtime.h>
#include <cuda_fp16.h>
#include <cstdint>

#define NB 64
#define NS 512
#define NTA 8
#define ND 768

// ------------------------------------------------------------------
// scratch (static __device__; no allocations allowed)
// ------------------------------------------------------------------
__device__ float g_mlen[NB], g_alen[NB];
__device__ float g_va[NB * ND], g_vs[NB * ND], g_ctx[NB * ND];
__device__ float g_scores[NB * NS];
__device__ float g_vns[NB * ND], g_vms[NB * ND];

// fp16 operands
__device__ __half g_Ah[(size_t)NB * NS * ND];
__device__ __half g_Bh[(size_t)ND * ND];   // [n][k] = W1_m[k][n]

// ------------------------------------------------------------------
// PTX helpers (baseline ISA only)
// ------------------------------------------------------------------
__device__ __forceinline__ uint32_t smem_u32(const void* p) {
    uint32_t a;
    asm("{ .reg .u64 t; cvta.to.shared.u64 t, %1; cvt.u32.u64 %0, t; }" : "=r"(a) : "l"(p));
    return a;
}
__device__ __forceinline__ void cp16(uint32_t dst, const void* src) {
    asm volatile("cp.async.cg.shared.global [%0], [%1], 16;" :: "r"(dst), "l"(src));
}
#define CP_COMMIT() asm volatile("cp.async.commit_group;" ::: "memory")
#define CP_WAIT1()  asm volatile("cp.async.wait_group 1;" ::: "memory")
#define CP_WAIT0()  asm volatile("cp.async.wait_group 0;" ::: "memory")

__device__ __forceinline__ void ldsm4(uint32_t& r0, uint32_t& r1, uint32_t& r2, uint32_t& r3,
                                      uint32_t addr) {
    asm volatile("ldmatrix.sync.aligned.m8n8.x4.shared.b16 {%0,%1,%2,%3}, [%4];"
                 : "=r"(r0), "=r"(r1), "=r"(r2), "=r"(r3) : "r"(addr));
}
__device__ __forceinline__ void mma16816(float* c, uint32_t a0, uint32_t a1, uint32_t a2,
                                         uint32_t a3, uint32_t b0, uint32_t b1) {
    asm volatile(
        "mma.sync.aligned.m16n8k16.row.col.f32.f16.f16.f32 "
        "{%0,%1,%2,%3}, {%4,%5,%6,%7}, {%8,%9}, {%0,%1,%2,%3};"
        : "+f"(c[0]), "+f"(c[1]), "+f"(c[2]), "+f"(c[3])
        : "r"(a0), "r"(a1), "r"(a2), "r"(a3), "r"(b0), "r"(b1));
}
__device__ __forceinline__ uint32_t tanh2_f16(uint32_t x) {
    uint32_t y;
    asm("tanh.approx.f16x2 %0, %1;" : "=r"(y) : "r"(x));
    return y;
}

// ------------------------------------------------------------------
// fused init: blocks [0,NB) = lengths; blocks [NB, NB+576) = W1_m transpose
// ------------------------------------------------------------------
__global__ __launch_bounds__(256) void k_init(const int* __restrict__ ids,
                                              const int* __restrict__ tids,
                                              const float* __restrict__ W1) {
    if (blockIdx.x < NB) {
        int b = blockIdx.x;
        __shared__ int sm[256];
        int tid = threadIdx.x;
        int c = 0;
        for (int s = tid; s < NS; s += 256) c += (ids[b * NS + s] != 0);
        sm[tid] = c;
        __syncthreads();
        for (int o = 128; o > 0; o >>= 1) {
            if (tid < o) sm[tid] += sm[tid + o];
            __syncthreads();
        }
        if (tid == 0) {
            g_mlen[b] = fmaxf((float)sm[0], 1.0f);
            int a = 0;
            for (int t = 0; t < NTA; t++) a += (tids[b * NTA + t] != 0);
            g_alen[b] = fmaxf((float)a, 1.0f);
        }
    } else {
        __shared__ float t[32][33];
        int blk = blockIdx.x - NB;            // 0..575 = 24x24
        int k0 = (blk % 24) * 32, n0 = (blk / 24) * 32;
        int tx = threadIdx.x & 31, ty = threadIdx.x >> 5;   // 32 x 8
        for (int i = ty; i < 32; i += 8)
            t[i][tx] = W1[(size_t)(k0 + i) * ND + n0 + tx];
        __syncthreads();
        for (int i = ty; i < 32; i += 8)
            g_Bh[(size_t)(n0 + i) * ND + k0 + tx] = __float2half_rn(t[tx][i]);
    }
}

// ------------------------------------------------------------------
// means + fp16 convert of memory (single 100MB pass)  [R7 form]
// ------------------------------------------------------------------
__global__ __launch_bounds__(512) void k_means(const float* __restrict__ mem,
                                               const float* __restrict__ asp) {
    __shared__ float sp[4][128];
    int b = blockIdx.y;
    int tid = threadIdx.x;
    int d = blockIdx.x * 128 + (tid & 127);
    int q = tid >> 7;
    float acc = 0.f;
    const float* p = mem + ((size_t)b * NS + q * 128) * ND + d;
    __half* ah = g_Ah + ((size_t)b * NS + q * 128) * ND + d;
#pragma unroll 8
    for (int s = 0; s < 128; s++) {
        float v = p[(size_t)s * ND];
        acc += v;
        ah[(size_t)s * ND] = __float2half_rn(v);
    }
    sp[q][tid & 127] = acc;
    __syncthreads();
    if (q == 0) {
        float tot = sp[0][tid] + sp[1][tid] + sp[2][tid] + sp[3][tid];
        g_vs[b * ND + d] = tot / g_mlen[b];
        float a = 0.f;
        const float* ap = asp + ((size_t)b * NTA) * ND + d;
#pragma unroll
        for (int t = 0; t < NTA; t++) a += ap[(size_t)t * ND];
        g_va[b * ND + d] = a / g_alen[b];
    }
}

// ------------------------------------------------------------------
// ctx = v_a @ W1_a + v_s @ W1_s + b1
// grid (ND/128, NB/4), 512 thr = 128 d x 4 q (2 mats x 2 k-halves); 4 b's/thread
// ------------------------------------------------------------------
__global__ __launch_bounds__(512) void k_ctx(const float* __restrict__ W1,
                                             const float* __restrict__ b1) {
    __shared__ float sp[4][128][4];
    int tid = threadIdx.x;
    int dt = tid & 127;
    int d = blockIdx.x * 128 + dt;
    int q = tid >> 7;                     // 0,1 -> Wa halves; 2,3 -> Ws halves
    int b0 = blockIdx.y * 4;
    const float* W = W1 + (size_t)(1 + (q >> 1)) * ND * ND + d;
    const float* vb = ((q >> 1) ? g_vs : g_va) + (size_t)b0 * ND;
    int k0 = (q & 1) * 384;
    float acc[4] = {0.f, 0.f, 0.f, 0.f};
#pragma unroll 4
    for (int k = 0; k < 384; k++) {
        float w = W[(size_t)(k0 + k) * ND];
        acc[0] = fmaf(vb[k0 + k], w, acc[0]);
        acc[1] = fmaf(vb[ND + k0 + k], w, acc[1]);
        acc[2] = fmaf(vb[2 * ND + k0 + k], w, acc[2]);
        acc[3] = fmaf(vb[3 * ND + k0 + k], w, acc[3]);
    }
#pragma unroll
    for (int i = 0; i < 4; i++) sp[q][dt][i] = acc[i];
    __syncthreads();
    if (q == 0) {
        float bb = b1[d];
#pragma unroll
        for (int i = 0; i < 4; i++) {
            float s = sp[0][dt][i] + sp[1][dt][i] + sp[2][dt][i] + sp[3][dt][i] + bb;
            g_ctx[(b0 + i) * ND + d] = s;
        }
    }
}

// ------------------------------------------------------------------
// fused scores: mma.sync fp16 GEMM + tanh/w2 epilogue  [R7 form]
// ------------------------------------------------------------------
#define MT 128
#define NTILE 128
#define KC 64
#define NCHUNKS (ND / NTILE)   // 6
#define KSTEPS (ND / KC)       // 12
#define APAD 144

#define OFF_A 0
#define OFF_B 18432
#define BUFSZ 36864
#define OFF_CTX (2 * BUFSZ)
#define OFF_W2  (OFF_CTX + 3072)
#define OFF_RED (OFF_W2 + 3072)
#define SMEMSZ  (OFF_RED + 1024)

struct ScoreCtx {
    const __half* gA;
    uint32_t sbase;
};

__device__ __forceinline__ void stage_tiles(const ScoreCtx& sc, int nbase, int k0, int buf) {
    int tid = threadIdx.x;
    uint32_t sb = sc.sbase + buf * BUFSZ;
#pragma unroll
    for (int t = 0; t < 4; t++) {
        int i = tid + t * 256;
        int r = i >> 3, c = i & 7;
        uint32_t d = sb + r * APAD + c * 16;
        cp16(d + OFF_A, sc.gA + (size_t)r * ND + k0 + c * 8);
        cp16(d + OFF_B, g_Bh + (size_t)(nbase + r) * ND + k0 + c * 8);
    }
}

__global__ void __launch_bounds__(256, 2) k_scores(const float* __restrict__ w2) {
    extern __shared__ char smem[];
    const int tid = threadIdx.x;
    const int b = blockIdx.y;
    const int s0 = blockIdx.x * MT;
    const int lane = tid & 31, wid = tid >> 5;
    const int warp_m = wid & 3, warp_n = wid >> 2;

    float* sctx = (float*)(smem + OFF_CTX);
    float* sw2p = (float*)(smem + OFF_W2);
    for (int i = tid; i < ND; i += 256) {
        sctx[i] = g_ctx[b * ND + i];
        sw2p[i] = w2[i];
    }

    ScoreCtx sc;
    sc.gA = g_Ah + ((size_t)b * NS + s0) * ND;
    sc.sbase = smem_u32(smem);

    const float mlen = g_mlen[b];
    float loc[2][2], rowsum[2][2];
#pragma unroll
    for (int mt = 0; mt < 2; mt++)
#pragma unroll
        for (int h = 0; h < 2; h++) {
            float srow = (float)(s0 + warp_m * 32 + mt * 16 + h * 8 + (lane >> 2));
            loc[mt][h] = (srow < mlen) ? (1.0f - srow / mlen) : 1.0f;
            rowsum[mt][h] = 0.f;
        }

    const int a_row = warp_m * 32 + (lane & 7) + ((lane >> 3) & 1) * 8;
    const int a_halfoff = (lane >> 4) * 16;
    const int b_row = warp_n * 64 + (lane & 7) + (lane >> 4) * 8;
    const int b_halfoff = ((lane >> 3) & 1) * 16;

    __syncthreads();

    stage_tiles(sc, 0, 0, 0);
    CP_COMMIT();

    for (int chunk = 0; chunk < NCHUNKS; chunk++) {
        const int nbase = chunk * NTILE;
        float acc[2][8][4];
#pragma unroll
        for (int mt = 0; mt < 2; mt++)
#pragma unroll
            for (int nt = 0; nt < 8; nt++)
#pragma unroll
                for (int j = 0; j < 4; j++) acc[mt][nt][j] = 0.f;

        for (int ks = 0; ks < KSTEPS; ks++) {
            const int buf = ks & 1;
            if (ks + 1 < KSTEPS) {
                stage_tiles(sc, nbase, (ks + 1) * KC, buf ^ 1);
                CP_COMMIT();
                CP_WAIT1();
            } else {
                CP_WAIT0();
            }
            __syncthreads();

            const uint32_t sb = sc.sbase + buf * BUFSZ;
#pragma unroll
            for (int kk = 0; kk < 4; kk++) {
                const int kb = kk * 32;
                uint32_t ar[2][4], br[4][4];
#pragma unroll
                for (int mt = 0; mt < 2; mt++)
                    ldsm4(ar[mt][0], ar[mt][1], ar[mt][2], ar[mt][3],
                          sb + OFF_A + (a_row + mt * 16) * APAD + kb + a_halfoff);
#pragma unroll
                for (int nt2 = 0; nt2 < 4; nt2++)
                    ldsm4(br[nt2][0], br[nt2][1], br[nt2][2], br[nt2][3],
                          sb + OFF_B + (b_row + nt2 * 16) * APAD + kb + b_halfoff);
#pragma unroll
                for (int mt = 0; mt < 2; mt++)
#pragma unroll
                    for (int nt2 = 0; nt2 < 4; nt2++)
#pragma unroll
                        for (int s = 0; s < 2; s++)
                            mma16816(acc[mt][nt2 * 2 + s], ar[mt][0], ar[mt][1], ar[mt][2],
                                     ar[mt][3], br[nt2][2 * s], br[nt2][2 * s + 1]);
            }
            __syncthreads();
        }

        if (chunk + 1 < NCHUNKS) {
            stage_tiles(sc, nbase + NTILE, 0, 0);
            CP_COMMIT();
        }

#pragma unroll
        for (int mt = 0; mt < 2; mt++) {
#pragma unroll
            for (int nt = 0; nt < 8; nt++) {
                const int c0 = nbase + warp_n * 64 + nt * 8 + (lane & 3) * 2;
                const float2 cx = *(const float2*)&sctx[c0];
                const float2 wv = *(const float2*)&sw2p[c0];
                {
                    float u0 = fmaf(loc[mt][0], acc[mt][nt][0], cx.x);
                    float u1 = fmaf(loc[mt][0], acc[mt][nt][1], cx.y);
                    __half2 hp = __floats2half2_rn(u0, u1);
                    uint32_t th = tanh2_f16(*(uint32_t*)&hp);
                    float2 tf = __half22float2(*(__half2*)&th);
                    rowsum[mt][0] = fmaf(tf.x, wv.x, fmaf(tf.y, wv.y, rowsum[mt][0]));
                }
                {
                    float u2 = fmaf(loc[mt][1], acc[mt][nt][2], cx.x);
                    float u3 = fmaf(loc[mt][1], acc[mt][nt][3], cx.y);
                    __half2 hp = __floats2half2_rn(u2, u3);
                    uint32_t th = tanh2_f16(*(uint32_t*)&hp);
                    float2 tf = __half22float2(*(__half2*)&th);
                    rowsum[mt][1] = fmaf(tf.x, wv.x, fmaf(tf.y, wv.y, rowsum[mt][1]));
                }
            }
        }
    }

    float* red = (float*)(smem + OFF_RED);
#pragma unroll
    for (int mt = 0; mt < 2; mt++)
#pragma unroll
        for (int h = 0; h < 2; h++) {
            float v = rowsum[mt][h];
            v += __shfl_xor_sync(0xffffffffu, v, 1);
            v += __shfl_xor_sync(0xffffffffu, v, 2);
            if ((lane & 3) == 0) {
                int lrow = warp_m * 32 + mt * 16 + h * 8 + (lane >> 2);
                red[lrow * 2 + warp_n] = v;
            }
        }
    __syncthreads();
    if (tid < MT)
        g_scores[b * NS + s0 + tid] = red[tid * 2] + red[tid * 2 + 1];
}

// ------------------------------------------------------------------
// softmax + v_ts + v_ns  (512 threads; reads fp16 memory copy) [R7 form]
// ------------------------------------------------------------------
__global__ __launch_bounds__(512) void k_soft_vts() {
    int b = blockIdx.x;
    int tid = threadIdx.x;
    __shared__ float sw[NS];
    __shared__ float red[512];
    __shared__ float sp[2][256];
    float mlen = g_mlen[b];

    float v = g_scores[b * NS + tid];
    red[tid] = v;
    __syncthreads();
    for (int o = 256; o > 0; o >>= 1) {
        if (tid < o) red[tid] = fmaxf(red[tid], red[tid + o]);
        __syncthreads();
    }
    float m = red[0];
    __syncthreads();
    float e = expf(v - m);
    red[tid] = e;
    __syncthreads();
    for (int o = 256; o > 0; o >>= 1) {
        if (tid < o) red[tid] += red[tid + o];
        __syncthreads();
    }
    float inv = 1.0f / red[0];
    __syncthreads();
    float s = (float)tid;
    float l = (s < mlen) ? (1.0f - s / mlen) : 1.0f;
    sw[tid] = e * inv * l;
    __syncthreads();

    int dq = tid >> 8;
    int dd = tid & 255;
    for (int dc = 0; dc < 3; dc++) {
        int d = dc * 256 + dd;
        const __half* p = g_Ah + ((size_t)b * NS + dq * 256) * ND + d;
        float acc = 0.f;
#pragma unroll 8
        for (int s2 = 0; s2 < 256; s2++)
            acc = fmaf(sw[dq * 256 + s2], __half2float(p[(size_t)s2 * ND]), acc);
        sp[dq][dd] = acc;
        __syncthreads();
        if (dq == 0)
            g_vns[b * ND + d] = sp[0][dd] + sp[1][dd] + g_vs[b * ND + d];
        __syncthreads();
    }
}

// ------------------------------------------------------------------
// v_ms = tanh(v_ns @ Wm + bm)
// grid (ND/128, NB/4), 512 thr = 128 d x 4 k-quarters; 4 b's/thread
// ------------------------------------------------------------------
__global__ __launch_bounds__(512) void k_vms(const float* __restrict__ Wm,
                                             const float* __restrict__ bm) {
    __shared__ float sp[4][128][4];
    int tid = threadIdx.x;
    int dt = tid & 127;
    int d = blockIdx.x * 128 + dt;
    int q = tid >> 7;
    int b0 = blockIdx.y * 4;
    const float* vb = g_vns + (size_t)b0 * ND;
    int k0 = q * 192;
    float acc[4] = {0.f, 0.f, 0.f, 0.f};
#pragma unroll 4
    for (int k = 0; k < 192; k++) {
        float w = Wm[(size_t)(k0 + k) * ND + d];
        acc[0] = fmaf(vb[k0 + k], w, acc[0]);
        acc[1] = fmaf(vb[ND + k0 + k], w, acc[1]);
        acc[2] = fmaf(vb[2 * ND + k0 + k], w, acc[2]);
        acc[3] = fmaf(vb[3 * ND + k0 + k], w, acc[3]);
    }
#pragma unroll
    for (int i = 0; i < 4; i++) sp[q][dt][i] = acc[i];
    __syncthreads();
    if (q == 0) {
        float bb = bm[d];
#pragma unroll
        for (int i = 0; i < 4; i++) {
            float s = sp[0][dt][i] + sp[1][dt][i] + sp[2][dt][i] + sp[3][dt][i] + bb;
            g_vms[(b0 + i) * ND + d] = tanhf(s);
        }
    }
}

// ------------------------------------------------------------------
// logits
// ------------------------------------------------------------------
__global__ void k_logits(const float* __restrict__ Wd,
                         const float* __restrict__ bd,
                         float* __restrict__ out) {
    int t = threadIdx.x;
    if (t >= NB * 3) return;
    int b = t / 3, j = t % 3;
    float acc = bd[j];
    const float* v = g_vms + b * ND;
#pragma unroll 4
    for (int d = 0; d < ND; d++) acc = fmaf(v[d], Wd[d * 3 + j], acc);
    out[b * 3 + j] = acc;
}

// ------------------------------------------------------------------
// launch
// ------------------------------------------------------------------
extern "C" void kernel_launch(void* const* d_in, const int* in_sizes, int n_in,
                              void* d_out, int out_size) {
    (void)in_sizes; (void)n_in; (void)out_size;
    const float* mem  = (const float*)d_in[0];
    const float* asp  = (const float*)d_in[1];
    const int* ids    = (const int*)d_in[2];
    const int* tids   = (const int*)d_in[3];
    const float* W1 = (const float*)d_in[4];
    const float* b1 = (const float*)d_in[5];
    const float* w2 = (const float*)d_in[6];
    const float* Wm = (const float*)d_in[7];
    const float* bm = (const float*)d_in[8];
    const float* Wd = (const float*)d_in[9];
    const float* bd = (const float*)d_in[10];
    float* out = (float*)d_out;

    cudaFuncSetAttribute(k_scores, cudaFuncAttributeMaxDynamicSharedMemorySize, SMEMSZ);

    k_init<<<NB + 576, 256>>>(ids, tids, W1);
    k_means<<<dim3(ND / 128, NB), 512>>>(mem, asp);
    k_ctx<<<dim3(ND / 128, NB / 4), 512>>>(W1, b1);
    k_scores<<<dim3(NS / MT, NB), 256, SMEMSZ>>>(w2);     // 4th launch -> ncu capture
    k_soft_vts<<<NB, 512>>>();
    k_vms<<<dim3(ND / 128, NB / 4), 512>>>(Wm, bm);
    k_logits<<<1, 256>>>(Wd, bd, out);
}

// round 10
// speedup vs baseline: 1.4307x; 1.2420x over previous
#include <cuda_runtime.h>
#include <cuda_fp16.h>
#include <cstdint>

#define NB 64
#define NS 512
#define NTA 8
#define ND 768

// ------------------------------------------------------------------
// scratch (static __device__; no allocations allowed)
// ------------------------------------------------------------------
__device__ float g_mlen[NB], g_alen[NB];
__device__ float g_va[NB * ND], g_vs[NB * ND], g_ctx[NB * ND];
__device__ float g_scores[NB * NS];
__device__ float g_sw[NB * NS];
__device__ float g_vns[NB * ND], g_vms[NB * ND];

// fp16 operands
__device__ __half g_Ah[(size_t)NB * NS * ND];
__device__ __half g_Bh[(size_t)ND * ND];   // [n][k] = W1_m[k][n]

// ------------------------------------------------------------------
// PTX helpers (baseline ISA only)
// ------------------------------------------------------------------
__device__ __forceinline__ uint32_t smem_u32(const void* p) {
    uint32_t a;
    asm("{ .reg .u64 t; cvta.to.shared.u64 t, %1; cvt.u32.u64 %0, t; }" : "=r"(a) : "l"(p));
    return a;
}
__device__ __forceinline__ void cp16(uint32_t dst, const void* src) {
    asm volatile("cp.async.cg.shared.global [%0], [%1], 16;" :: "r"(dst), "l"(src));
}
#define CP_COMMIT() asm volatile("cp.async.commit_group;" ::: "memory")
#define CP_WAIT1()  asm volatile("cp.async.wait_group 1;" ::: "memory")
#define CP_WAIT0()  asm volatile("cp.async.wait_group 0;" ::: "memory")

__device__ __forceinline__ void ldsm4(uint32_t& r0, uint32_t& r1, uint32_t& r2, uint32_t& r3,
                                      uint32_t addr) {
    asm volatile("ldmatrix.sync.aligned.m8n8.x4.shared.b16 {%0,%1,%2,%3}, [%4];"
                 : "=r"(r0), "=r"(r1), "=r"(r2), "=r"(r3) : "r"(addr));
}
__device__ __forceinline__ void mma16816(float* c, uint32_t a0, uint32_t a1, uint32_t a2,
                                         uint32_t a3, uint32_t b0, uint32_t b1) {
    asm volatile(
        "mma.sync.aligned.m16n8k16.row.col.f32.f16.f16.f32 "
        "{%0,%1,%2,%3}, {%4,%5,%6,%7}, {%8,%9}, {%0,%1,%2,%3};"
        : "+f"(c[0]), "+f"(c[1]), "+f"(c[2]), "+f"(c[3])
        : "r"(a0), "r"(a1), "r"(a2), "r"(a3), "r"(b0), "r"(b1));
}
__device__ __forceinline__ uint32_t tanh2_f16(uint32_t x) {
    uint32_t y;
    asm("tanh.approx.f16x2 %0, %1;" : "=r"(y) : "r"(x));
    return y;
}

// ------------------------------------------------------------------
// fused init: blocks [0,NB) = lengths; blocks [NB, NB+576) = W1_m transpose
// ------------------------------------------------------------------
__global__ __launch_bounds__(256) void k_init(const int* __restrict__ ids,
                                              const int* __restrict__ tids,
                                              const float* __restrict__ W1) {
    if (blockIdx.x < NB) {
        int b = blockIdx.x;
        __shared__ int sm[256];
        int tid = threadIdx.x;
        int c = 0;
        for (int s = tid; s < NS; s += 256) c += (ids[b * NS + s] != 0);
        sm[tid] = c;
        __syncthreads();
        for (int o = 128; o > 0; o >>= 1) {
            if (tid < o) sm[tid] += sm[tid + o];
            __syncthreads();
        }
        if (tid == 0) {
            g_mlen[b] = fmaxf((float)sm[0], 1.0f);
            int a = 0;
            for (int t = 0; t < NTA; t++) a += (tids[b * NTA + t] != 0);
            g_alen[b] = fmaxf((float)a, 1.0f);
        }
    } else {
        __shared__ float t[32][33];
        int blk = blockIdx.x - NB;            // 0..575 = 24x24
        int k0 = (blk % 24) * 32, n0 = (blk / 24) * 32;
        int tx = threadIdx.x & 31, ty = threadIdx.x >> 5;   // 32 x 8
        for (int i = ty; i < 32; i += 8)
            t[i][tx] = W1[(size_t)(k0 + i) * ND + n0 + tx];
        __syncthreads();
        for (int i = ty; i < 32; i += 8)
            g_Bh[(size_t)(n0 + i) * ND + k0 + tx] = __float2half_rn(t[tx][i]);
    }
}

// ------------------------------------------------------------------
// means + fp16 convert of memory (single 100MB pass)  [R7 form]
// ------------------------------------------------------------------
__global__ __launch_bounds__(512) void k_means(const float* __restrict__ mem,
                                               const float* __restrict__ asp) {
    __shared__ float sp[4][128];
    int b = blockIdx.y;
    int tid = threadIdx.x;
    int d = blockIdx.x * 128 + (tid & 127);
    int q = tid >> 7;
    float acc = 0.f;
    const float* p = mem + ((size_t)b * NS + q * 128) * ND + d;
    __half* ah = g_Ah + ((size_t)b * NS + q * 128) * ND + d;
#pragma unroll 8
    for (int s = 0; s < 128; s++) {
        float v = p[(size_t)s * ND];
        acc += v;
        ah[(size_t)s * ND] = __float2half_rn(v);
    }
    sp[q][tid & 127] = acc;
    __syncthreads();
    if (q == 0) {
        float tot = sp[0][tid] + sp[1][tid] + sp[2][tid] + sp[3][tid];
        g_vs[b * ND + d] = tot / g_mlen[b];
        float a = 0.f;
        const float* ap = asp + ((size_t)b * NTA) * ND + d;
#pragma unroll
        for (int t = 0; t < NTA; t++) a += ap[(size_t)t * ND];
        g_va[b * ND + d] = a / g_alen[b];
    }
}

// ------------------------------------------------------------------
// ctx = v_a @ W1_a + v_s @ W1_s + b1
// grid (ND/128, NB/2), 512 thr = 128 d x 4 q (2 mats x 2 k-halves); 2 b's/thread
// ------------------------------------------------------------------
__global__ __launch_bounds__(512) void k_ctx(const float* __restrict__ W1,
                                             const float* __restrict__ b1) {
    __shared__ float sp[4][128][2];
    int tid = threadIdx.x;
    int dt = tid & 127;
    int d = blockIdx.x * 128 + dt;
    int q = tid >> 7;                     // 0,1 -> Wa halves; 2,3 -> Ws halves
    int b0 = blockIdx.y * 2;
    const float* W = W1 + (size_t)(1 + (q >> 1)) * ND * ND + d;
    const float* vb = ((q >> 1) ? g_vs : g_va) + (size_t)b0 * ND;
    int k0 = (q & 1) * 384;
    float a0 = 0.f, a1 = 0.f;
#pragma unroll 4
    for (int k = 0; k < 384; k++) {
        float w = W[(size_t)(k0 + k) * ND];
        a0 = fmaf(vb[k0 + k], w, a0);
        a1 = fmaf(vb[ND + k0 + k], w, a1);
    }
    sp[q][dt][0] = a0;
    sp[q][dt][1] = a1;
    __syncthreads();
    if (q == 0) {
        float bb = b1[d];
#pragma unroll
        for (int i = 0; i < 2; i++) {
            float s = sp[0][dt][i] + sp[1][dt][i] + sp[2][dt][i] + sp[3][dt][i] + bb;
            g_ctx[(b0 + i) * ND + d] = s;
        }
    }
}

// ------------------------------------------------------------------
// fused scores: mma.sync fp16 GEMM + tanh/w2 epilogue  [R7 form]
// ------------------------------------------------------------------
#define MT 128
#define NTILE 128
#define KC 64
#define NCHUNKS (ND / NTILE)   // 6
#define KSTEPS (ND / KC)       // 12
#define APAD 144

#define OFF_A 0
#define OFF_B 18432
#define BUFSZ 36864
#define OFF_CTX (2 * BUFSZ)
#define OFF_W2  (OFF_CTX + 3072)
#define OFF_RED (OFF_W2 + 3072)
#define SMEMSZ  (OFF_RED + 1024)

struct ScoreCtx {
    const __half* gA;
    uint32_t sbase;
};

__device__ __forceinline__ void stage_tiles(const ScoreCtx& sc, int nbase, int k0, int buf) {
    int tid = threadIdx.x;
    uint32_t sb = sc.sbase + buf * BUFSZ;
#pragma unroll
    for (int t = 0; t < 4; t++) {
        int i = tid + t * 256;
        int r = i >> 3, c = i & 7;
        uint32_t d = sb + r * APAD + c * 16;
        cp16(d + OFF_A, sc.gA + (size_t)r * ND + k0 + c * 8);
        cp16(d + OFF_B, g_Bh + (size_t)(nbase + r) * ND + k0 + c * 8);
    }
}

__global__ void __launch_bounds__(256, 2) k_scores(const float* __restrict__ w2) {
    extern __shared__ char smem[];
    const int tid = threadIdx.x;
    const int b = blockIdx.y;
    const int s0 = blockIdx.x * MT;
    const int lane = tid & 31, wid = tid >> 5;
    const int warp_m = wid & 3, warp_n = wid >> 2;

    float* sctx = (float*)(smem + OFF_CTX);
    float* sw2p = (float*)(smem + OFF_W2);
    for (int i = tid; i < ND; i += 256) {
        sctx[i] = g_ctx[b * ND + i];
        sw2p[i] = w2[i];
    }

    ScoreCtx sc;
    sc.gA = g_Ah + ((size_t)b * NS + s0) * ND;
    sc.sbase = smem_u32(smem);

    const float mlen = g_mlen[b];
    float loc[2][2], rowsum[2][2];
#pragma unroll
    for (int mt = 0; mt < 2; mt++)
#pragma unroll
        for (int h = 0; h < 2; h++) {
            float srow = (float)(s0 + warp_m * 32 + mt * 16 + h * 8 + (lane >> 2));
            loc[mt][h] = (srow < mlen) ? (1.0f - srow / mlen) : 1.0f;
            rowsum[mt][h] = 0.f;
        }

    const int a_row = warp_m * 32 + (lane & 7) + ((lane >> 3) & 1) * 8;
    const int a_halfoff = (lane >> 4) * 16;
    const int b_row = warp_n * 64 + (lane & 7) + (lane >> 4) * 8;
    const int b_halfoff = ((lane >> 3) & 1) * 16;

    __syncthreads();

    stage_tiles(sc, 0, 0, 0);
    CP_COMMIT();

    for (int chunk = 0; chunk < NCHUNKS; chunk++) {
        const int nbase = chunk * NTILE;
        float acc[2][8][4];
#pragma unroll
        for (int mt = 0; mt < 2; mt++)
#pragma unroll
            for (int nt = 0; nt < 8; nt++)
#pragma unroll
                for (int j = 0; j < 4; j++) acc[mt][nt][j] = 0.f;

        for (int ks = 0; ks < KSTEPS; ks++) {
            const int buf = ks & 1;
            if (ks + 1 < KSTEPS) {
                stage_tiles(sc, nbase, (ks + 1) * KC, buf ^ 1);
                CP_COMMIT();
                CP_WAIT1();
            } else {
                CP_WAIT0();
            }
            __syncthreads();

            const uint32_t sb = sc.sbase + buf * BUFSZ;
#pragma unroll
            for (int kk = 0; kk < 4; kk++) {
                const int kb = kk * 32;
                uint32_t ar[2][4], br[4][4];
#pragma unroll
                for (int mt = 0; mt < 2; mt++)
                    ldsm4(ar[mt][0], ar[mt][1], ar[mt][2], ar[mt][3],
                          sb + OFF_A + (a_row + mt * 16) * APAD + kb + a_halfoff);
#pragma unroll
                for (int nt2 = 0; nt2 < 4; nt2++)
                    ldsm4(br[nt2][0], br[nt2][1], br[nt2][2], br[nt2][3],
                          sb + OFF_B + (b_row + nt2 * 16) * APAD + kb + b_halfoff);
#pragma unroll
                for (int mt = 0; mt < 2; mt++)
#pragma unroll
                    for (int nt2 = 0; nt2 < 4; nt2++)
#pragma unroll
                        for (int s = 0; s < 2; s++)
                            mma16816(acc[mt][nt2 * 2 + s], ar[mt][0], ar[mt][1], ar[mt][2],
                                     ar[mt][3], br[nt2][2 * s], br[nt2][2 * s + 1]);
            }
            __syncthreads();
        }

        if (chunk + 1 < NCHUNKS) {
            stage_tiles(sc, nbase + NTILE, 0, 0);
            CP_COMMIT();
        }

#pragma unroll
        for (int mt = 0; mt < 2; mt++) {
#pragma unroll
            for (int nt = 0; nt < 8; nt++) {
                const int c0 = nbase + warp_n * 64 + nt * 8 + (lane & 3) * 2;
                const float2 cx = *(const float2*)&sctx[c0];
                const float2 wv = *(const float2*)&sw2p[c0];
                {
                    float u0 = fmaf(loc[mt][0], acc[mt][nt][0], cx.x);
                    float u1 = fmaf(loc[mt][0], acc[mt][nt][1], cx.y);
                    __half2 hp = __floats2half2_rn(u0, u1);
                    uint32_t th = tanh2_f16(*(uint32_t*)&hp);
                    float2 tf = __half22float2(*(__half2*)&th);
                    rowsum[mt][0] = fmaf(tf.x, wv.x, fmaf(tf.y, wv.y, rowsum[mt][0]));
                }
                {
                    float u2 = fmaf(loc[mt][1], acc[mt][nt][2], cx.x);
                    float u3 = fmaf(loc[mt][1], acc[mt][nt][3], cx.y);
                    __half2 hp = __floats2half2_rn(u2, u3);
                    uint32_t th = tanh2_f16(*(uint32_t*)&hp);
                    float2 tf = __half22float2(*(__half2*)&th);
                    rowsum[mt][1] = fmaf(tf.x, wv.x, fmaf(tf.y, wv.y, rowsum[mt][1]));
                }
            }
        }
    }

    float* red = (float*)(smem + OFF_RED);
#pragma unroll
    for (int mt = 0; mt < 2; mt++)
#pragma unroll
        for (int h = 0; h < 2; h++) {
            float v = rowsum[mt][h];
            v += __shfl_xor_sync(0xffffffffu, v, 1);
            v += __shfl_xor_sync(0xffffffffu, v, 2);
            if ((lane & 3) == 0) {
                int lrow = warp_m * 32 + mt * 16 + h * 8 + (lane >> 2);
                red[lrow * 2 + warp_n] = v;
            }
        }
    __syncthreads();
    if (tid < MT)
        g_scores[b * NS + s0 + tid] = red[tid * 2] + red[tid * 2 + 1];
}

// ------------------------------------------------------------------
// softmax -> g_sw  (64 CTAs, tiny)
// ------------------------------------------------------------------
__global__ __launch_bounds__(512) void k_soft() {
    int b = blockIdx.x;
    int tid = threadIdx.x;
    __shared__ float red[512];
    float mlen = g_mlen[b];

    float v = g_scores[b * NS + tid];
    red[tid] = v;
    __syncthreads();
    for (int o = 256; o > 0; o >>= 1) {
        if (tid < o) red[tid] = fmaxf(red[tid], red[tid + o]);
        __syncthreads();
    }
    float m = red[0];
    __syncthreads();
    float e = expf(v - m);
    red[tid] = e;
    __syncthreads();
    for (int o = 256; o > 0; o >>= 1) {
        if (tid < o) red[tid] += red[tid + o];
        __syncthreads();
    }
    float inv = 1.0f / red[0];
    float s = (float)tid;
    float l = (s < mlen) ? (1.0f - s / mlen) : 1.0f;
    g_sw[b * NS + tid] = e * inv * l;
}

// ------------------------------------------------------------------
// v_ts + v_ns:  grid (3, 64) -> 192 CTAs, each covers 256-d chunk
// ------------------------------------------------------------------
__global__ __launch_bounds__(512) void k_vts() {
    int b = blockIdx.y;
    int dc = blockIdx.x;
    int tid = threadIdx.x;
    __shared__ float sw[NS];
    __shared__ float sp[2][256];
    sw[tid] = g_sw[b * NS + tid];
    __syncthreads();

    int dq = tid >> 8;
    int dd = tid & 255;
    int d = dc * 256 + dd;
    const __half* p = g_Ah + ((size_t)b * NS + dq * 256) * ND + d;
    float acc = 0.f;
#pragma unroll 8
    for (int s2 = 0; s2 < 256; s2++)
        acc = fmaf(sw[dq * 256 + s2], __half2float(p[(size_t)s2 * ND]), acc);
    sp[dq][dd] = acc;
    __syncthreads();
    if (dq == 0)
        g_vns[b * ND + d] = sp[0][dd] + sp[1][dd] + g_vs[b * ND + d];
}

// ------------------------------------------------------------------
// v_ms = tanh(v_ns @ Wm + bm)
// grid (ND/128, NB/2), 512 thr = 128 d x 4 k-quarters; 2 b's/thread
// ------------------------------------------------------------------
__global__ __launch_bounds__(512) void k_vms(const float* __restrict__ Wm,
                                             const float* __restrict__ bm) {
    __shared__ float sp[4][128][2];
    int tid = threadIdx.x;
    int dt = tid & 127;
    int d = blockIdx.x * 128 + dt;
    int q = tid >> 7;
    int b0 = blockIdx.y * 2;
    const float* vb = g_vns + (size_t)b0 * ND;
    int k0 = q * 192;
    float a0 = 0.f, a1 = 0.f;
#pragma unroll 4
    for (int k = 0; k < 192; k++) {
        float w = Wm[(size_t)(k0 + k) * ND + d];
        a0 = fmaf(vb[k0 + k], w, a0);
        a1 = fmaf(vb[ND + k0 + k], w, a1);
    }
    sp[q][dt][0] = a0;
    sp[q][dt][1] = a1;
    __syncthreads();
    if (q == 0) {
        float bb = bm[d];
#pragma unroll
        for (int i = 0; i < 2; i++) {
            float s = sp[0][dt][i] + sp[1][dt][i] + sp[2][dt][i] + sp[3][dt][i] + bb;
            g_vms[(b0 + i) * ND + d] = tanhf(s);
        }
    }
}

// ------------------------------------------------------------------
// logits
// ------------------------------------------------------------------
__global__ void k_logits(const float* __restrict__ Wd,
                         const float* __restrict__ bd,
                         float* __restrict__ out) {
    int t = threadIdx.x;
    if (t >= NB * 3) return;
    int b = t / 3, j = t % 3;
    float acc = bd[j];
    const float* v = g_vms + b * ND;
#pragma unroll 4
    for (int d = 0; d < ND; d++) acc = fmaf(v[d], Wd[d * 3 + j], acc);
    out[b * 3 + j] = acc;
}

// ------------------------------------------------------------------
// launch
// ------------------------------------------------------------------
extern "C" void kernel_launch(void* const* d_in, const int* in_sizes, int n_in,
                              void* d_out, int out_size) {
    (void)in_sizes; (void)n_in; (void)out_size;
    const float* mem  = (const float*)d_in[0];
    const float* asp  = (const float*)d_in[1];
    const int* ids    = (const int*)d_in[2];
    const int* tids   = (const int*)d_in[3];
    const float* W1 = (const float*)d_in[4];
    const float* b1 = (const float*)d_in[5];
    const float* w2 = (const float*)d_in[6];
    const float* Wm = (const float*)d_in[7];
    const float* bm = (const float*)d_in[8];
    const float* Wd = (const float*)d_in[9];
    const float* bd = (const float*)d_in[10];
    float* out = (float*)d_out;

    cudaFuncSetAttribute(k_scores, cudaFuncAttributeMaxDynamicSharedMemorySize, SMEMSZ);

    k_init<<<NB + 576, 256>>>(ids, tids, W1);
    k_means<<<dim3(ND / 128, NB), 512>>>(mem, asp);
    k_ctx<<<dim3(ND / 128, NB / 2), 512>>>(W1, b1);
    k_scores<<<dim3(NS / MT, NB), 256, SMEMSZ>>>(w2);     // 4th launch -> ncu capture
    k_soft<<<NB, 512>>>();
    k_vts<<<dim3(3, NB), 512>>>();
    k_vms<<<dim3(ND / 128, NB / 2), 512>>>(Wm, bm);
    k_logits<<<1, 256>>>(Wd, bd, out);
}

// round 11
// speedup vs baseline: 1.4663x; 1.0249x over previous
#include <cuda_runtime.h>
#include <cuda_fp16.h>
#include <cstdint>

#define NB 64
#define NS 512
#define NTA 8
#define ND 768

// ------------------------------------------------------------------
// scratch (static __device__; no allocations allowed)
// ------------------------------------------------------------------
__device__ float g_mlen[NB], g_alen[NB];
__device__ float g_va[NB * ND], g_vs[NB * ND], g_ctx[NB * ND];
__device__ float g_scores[NB * NS];
__device__ float g_vns[NB * ND], g_vms[NB * ND];

// fp16 operands
__device__ __half g_Ah[(size_t)NB * NS * ND];
__device__ __half g_Bh[(size_t)ND * ND];   // [n][k] = W1_m[k][n]

// ------------------------------------------------------------------
// PTX helpers (baseline ISA only)
// ------------------------------------------------------------------
__device__ __forceinline__ uint32_t smem_u32(const void* p) {
    uint32_t a;
    asm("{ .reg .u64 t; cvta.to.shared.u64 t, %1; cvt.u32.u64 %0, t; }" : "=r"(a) : "l"(p));
    return a;
}
__device__ __forceinline__ void cp16(uint32_t dst, const void* src) {
    asm volatile("cp.async.cg.shared.global [%0], [%1], 16;" :: "r"(dst), "l"(src));
}
#define CP_COMMIT() asm volatile("cp.async.commit_group;" ::: "memory")
#define CP_WAIT1()  asm volatile("cp.async.wait_group 1;" ::: "memory")
#define CP_WAIT0()  asm volatile("cp.async.wait_group 0;" ::: "memory")

__device__ __forceinline__ void ldsm4(uint32_t& r0, uint32_t& r1, uint32_t& r2, uint32_t& r3,
                                      uint32_t addr) {
    asm volatile("ldmatrix.sync.aligned.m8n8.x4.shared.b16 {%0,%1,%2,%3}, [%4];"
                 : "=r"(r0), "=r"(r1), "=r"(r2), "=r"(r3) : "r"(addr));
}
__device__ __forceinline__ void mma16816(float* c, uint32_t a0, uint32_t a1, uint32_t a2,
                                         uint32_t a3, uint32_t b0, uint32_t b1) {
    asm volatile(
        "mma.sync.aligned.m16n8k16.row.col.f32.f16.f16.f32 "
        "{%0,%1,%2,%3}, {%4,%5,%6,%7}, {%8,%9}, {%0,%1,%2,%3};"
        : "+f"(c[0]), "+f"(c[1]), "+f"(c[2]), "+f"(c[3])
        : "r"(a0), "r"(a1), "r"(a2), "r"(a3), "r"(b0), "r"(b1));
}
__device__ __forceinline__ uint32_t tanh2_f16(uint32_t x) {
    uint32_t y;
    asm("tanh.approx.f16x2 %0, %1;" : "=r"(y) : "r"(x));
    return y;
}

// ------------------------------------------------------------------
// k_head: fused means+convert / W1_m transpose / global lens
//   blocks [0,384): means for (b, d-block) — local lens, fp16 convert
//   blocks [384,960): W1_m transpose+fp16 (24x24 tiles)
//   blocks [960,1024): global g_mlen/g_alen for later kernels
// ------------------------------------------------------------------
__global__ __launch_bounds__(512) void k_head(const float* __restrict__ mem,
                                              const float* __restrict__ asp,
                                              const int* __restrict__ ids,
                                              const int* __restrict__ tids,
                                              const float* __restrict__ W1) {
    int blk = blockIdx.x;
    int tid = threadIdx.x;
    if (blk < 384) {
        int b = blk / 6;
        int db = blk % 6;
        __shared__ float sp[4][128];
        __shared__ float s_ml, s_al;
        // local lens (cheap 2KB re-read; removes cross-block dependency)
        float* red = &sp[0][0];
        red[tid] = (ids[b * NS + tid] != 0) ? 1.0f : 0.0f;
        __syncthreads();
        for (int o = 256; o > 0; o >>= 1) {
            if (tid < o) red[tid] += red[tid + o];
            __syncthreads();
        }
        if (tid == 0) {
            s_ml = fmaxf(red[0], 1.0f);
            int a = 0;
#pragma unroll
            for (int t = 0; t < NTA; t++) a += (tids[b * NTA + t] != 0);
            s_al = fmaxf((float)a, 1.0f);
        }
        __syncthreads();
        float mlen = s_ml, alen = s_al;
        __syncthreads();
        // means + fp16 convert
        int d = db * 128 + (tid & 127);
        int q = tid >> 7;
        float acc = 0.f;
        const float* p = mem + ((size_t)b * NS + q * 128) * ND + d;
        __half* ah = g_Ah + ((size_t)b * NS + q * 128) * ND + d;
#pragma unroll 8
        for (int s = 0; s < 128; s++) {
            float v = p[(size_t)s * ND];
            acc += v;
            ah[(size_t)s * ND] = __float2half_rn(v);
        }
        sp[q][tid & 127] = acc;
        __syncthreads();
        if (q == 0) {
            float tot = sp[0][tid] + sp[1][tid] + sp[2][tid] + sp[3][tid];
            g_vs[b * ND + d] = tot / mlen;
            float a = 0.f;
            const float* ap = asp + ((size_t)b * NTA) * ND + d;
#pragma unroll
            for (int t = 0; t < NTA; t++) a += ap[(size_t)t * ND];
            g_va[b * ND + d] = a / alen;
        }
    } else if (blk < 960) {
        __shared__ float t[32][33];
        int bb = blk - 384;                 // 0..575 = 24x24
        int k0 = (bb % 24) * 32, n0 = (bb / 24) * 32;
        int tx = tid & 31, ty = tid >> 5;   // 32 x 16
        for (int i = ty; i < 32; i += 16)
            t[i][tx] = W1[(size_t)(k0 + i) * ND + n0 + tx];
        __syncthreads();
        for (int i = ty; i < 32; i += 16)
            g_Bh[(size_t)(n0 + i) * ND + k0 + tx] = __float2half_rn(t[tx][i]);
    } else {
        int b = blk - 960;
        __shared__ float red[512];
        red[tid] = (ids[b * NS + tid] != 0) ? 1.0f : 0.0f;
        __syncthreads();
        for (int o = 256; o > 0; o >>= 1) {
            if (tid < o) red[tid] += red[tid + o];
            __syncthreads();
        }
        if (tid == 0) {
            g_mlen[b] = fmaxf(red[0], 1.0f);
            int a = 0;
#pragma unroll
            for (int t = 0; t < NTA; t++) a += (tids[b * NTA + t] != 0);
            g_alen[b] = fmaxf((float)a, 1.0f);
        }
    }
}

// ------------------------------------------------------------------
// ctx = v_a @ W1_a + v_s @ W1_s + b1
// grid (ND/128, NB/2), 512 thr = 128 d x 4 q (2 mats x 2 k-halves); 2 b's/thread
// ------------------------------------------------------------------
__global__ __launch_bounds__(512) void k_ctx(const float* __restrict__ W1,
                                             const float* __restrict__ b1) {
    __shared__ float sp[4][128][2];
    int tid = threadIdx.x;
    int dt = tid & 127;
    int d = blockIdx.x * 128 + dt;
    int q = tid >> 7;                     // 0,1 -> Wa halves; 2,3 -> Ws halves
    int b0 = blockIdx.y * 2;
    const float* W = W1 + (size_t)(1 + (q >> 1)) * ND * ND + d;
    const float* vb = ((q >> 1) ? g_vs : g_va) + (size_t)b0 * ND;
    int k0 = (q & 1) * 384;
    float a0 = 0.f, a1 = 0.f;
#pragma unroll 4
    for (int k = 0; k < 384; k++) {
        float w = W[(size_t)(k0 + k) * ND];
        a0 = fmaf(vb[k0 + k], w, a0);
        a1 = fmaf(vb[ND + k0 + k], w, a1);
    }
    sp[q][dt][0] = a0;
    sp[q][dt][1] = a1;
    __syncthreads();
    if (q == 0) {
        float bb = b1[d];
#pragma unroll
        for (int i = 0; i < 2; i++) {
            float s = sp[0][dt][i] + sp[1][dt][i] + sp[2][dt][i] + sp[3][dt][i] + bb;
            g_ctx[(b0 + i) * ND + d] = s;
        }
    }
}

// ------------------------------------------------------------------
// fused scores: mma.sync fp16 GEMM + tanh/w2 epilogue  [at HMMA floor]
// ------------------------------------------------------------------
#define MT 128
#define NTILE 128
#define KC 64
#define NCHUNKS (ND / NTILE)   // 6
#define KSTEPS (ND / KC)       // 12
#define APAD 144

#define OFF_A 0
#define OFF_B 18432
#define BUFSZ 36864
#define OFF_CTX (2 * BUFSZ)
#define OFF_W2  (OFF_CTX + 3072)
#define OFF_RED (OFF_W2 + 3072)
#define SMEMSZ  (OFF_RED + 1024)

struct ScoreCtx {
    const __half* gA;
    uint32_t sbase;
};

__device__ __forceinline__ void stage_tiles(const ScoreCtx& sc, int nbase, int k0, int buf) {
    int tid = threadIdx.x;
    uint32_t sb = sc.sbase + buf * BUFSZ;
#pragma unroll
    for (int t = 0; t < 4; t++) {
        int i = tid + t * 256;
        int r = i >> 3, c = i & 7;
        uint32_t d = sb + r * APAD + c * 16;
        cp16(d + OFF_A, sc.gA + (size_t)r * ND + k0 + c * 8);
        cp16(d + OFF_B, g_Bh + (size_t)(nbase + r) * ND + k0 + c * 8);
    }
}

__global__ void __launch_bounds__(256, 2) k_scores(const float* __restrict__ w2) {
    extern __shared__ char smem[];
    const int tid = threadIdx.x;
    const int b = blockIdx.y;
    const int s0 = blockIdx.x * MT;
    const int lane = tid & 31, wid = tid >> 5;
    const int warp_m = wid & 3, warp_n = wid >> 2;

    float* sctx = (float*)(smem + OFF_CTX);
    float* sw2p = (float*)(smem + OFF_W2);
    for (int i = tid; i < ND; i += 256) {
        sctx[i] = g_ctx[b * ND + i];
        sw2p[i] = w2[i];
    }

    ScoreCtx sc;
    sc.gA = g_Ah + ((size_t)b * NS + s0) * ND;
    sc.sbase = smem_u32(smem);

    const float mlen = g_mlen[b];
    float loc[2][2], rowsum[2][2];
#pragma unroll
    for (int mt = 0; mt < 2; mt++)
#pragma unroll
        for (int h = 0; h < 2; h++) {
            float srow = (float)(s0 + warp_m * 32 + mt * 16 + h * 8 + (lane >> 2));
            loc[mt][h] = (srow < mlen) ? (1.0f - srow / mlen) : 1.0f;
            rowsum[mt][h] = 0.f;
        }

    const int a_row = warp_m * 32 + (lane & 7) + ((lane >> 3) & 1) * 8;
    const int a_halfoff = (lane >> 4) * 16;
    const int b_row = warp_n * 64 + (lane & 7) + (lane >> 4) * 8;
    const int b_halfoff = ((lane >> 3) & 1) * 16;

    __syncthreads();

    stage_tiles(sc, 0, 0, 0);
    CP_COMMIT();

    for (int chunk = 0; chunk < NCHUNKS; chunk++) {
        const int nbase = chunk * NTILE;
        float acc[2][8][4];
#pragma unroll
        for (int mt = 0; mt < 2; mt++)
#pragma unroll
            for (int nt = 0; nt < 8; nt++)
#pragma unroll
                for (int j = 0; j < 4; j++) acc[mt][nt][j] = 0.f;

        for (int ks = 0; ks < KSTEPS; ks++) {
            const int buf = ks & 1;
            if (ks + 1 < KSTEPS) {
                stage_tiles(sc, nbase, (ks + 1) * KC, buf ^ 1);
                CP_COMMIT();
                CP_WAIT1();
            } else {
                CP_WAIT0();
            }
            __syncthreads();

            const uint32_t sb = sc.sbase + buf * BUFSZ;
#pragma unroll
            for (int kk = 0; kk < 4; kk++) {
                const int kb = kk * 32;
                uint32_t ar[2][4], br[4][4];
#pragma unroll
                for (int mt = 0; mt < 2; mt++)
                    ldsm4(ar[mt][0], ar[mt][1], ar[mt][2], ar[mt][3],
                          sb + OFF_A + (a_row + mt * 16) * APAD + kb + a_halfoff);
#pragma unroll
                for (int nt2 = 0; nt2 < 4; nt2++)
                    ldsm4(br[nt2][0], br[nt2][1], br[nt2][2], br[nt2][3],
                          sb + OFF_B + (b_row + nt2 * 16) * APAD + kb + b_halfoff);
#pragma unroll
                for (int mt = 0; mt < 2; mt++)
#pragma unroll
                    for (int nt2 = 0; nt2 < 4; nt2++)
#pragma unroll
                        for (int s = 0; s < 2; s++)
                            mma16816(acc[mt][nt2 * 2 + s], ar[mt][0], ar[mt][1], ar[mt][2],
                                     ar[mt][3], br[nt2][2 * s], br[nt2][2 * s + 1]);
            }
            __syncthreads();
        }

        if (chunk + 1 < NCHUNKS) {
            stage_tiles(sc, nbase + NTILE, 0, 0);
            CP_COMMIT();
        }

#pragma unroll
        for (int mt = 0; mt < 2; mt++) {
#pragma unroll
            for (int nt = 0; nt < 8; nt++) {
                const int c0 = nbase + warp_n * 64 + nt * 8 + (lane & 3) * 2;
                const float2 cx = *(const float2*)&sctx[c0];
                const float2 wv = *(const float2*)&sw2p[c0];
                {
                    float u0 = fmaf(loc[mt][0], acc[mt][nt][0], cx.x);
                    float u1 = fmaf(loc[mt][0], acc[mt][nt][1], cx.y);
                    __half2 hp = __floats2half2_rn(u0, u1);
                    uint32_t th = tanh2_f16(*(uint32_t*)&hp);
                    float2 tf = __half22float2(*(__half2*)&th);
                    rowsum[mt][0] = fmaf(tf.x, wv.x, fmaf(tf.y, wv.y, rowsum[mt][0]));
                }
                {
                    float u2 = fmaf(loc[mt][1], acc[mt][nt][2], cx.x);
                    float u3 = fmaf(loc[mt][1], acc[mt][nt][3], cx.y);
                    __half2 hp = __floats2half2_rn(u2, u3);
                    uint32_t th = tanh2_f16(*(uint32_t*)&hp);
                    float2 tf = __half22float2(*(__half2*)&th);
                    rowsum[mt][1] = fmaf(tf.x, wv.x, fmaf(tf.y, wv.y, rowsum[mt][1]));
                }
            }
        }
    }

    float* red = (float*)(smem + OFF_RED);
#pragma unroll
    for (int mt = 0; mt < 2; mt++)
#pragma unroll
        for (int h = 0; h < 2; h++) {
            float v = rowsum[mt][h];
            v += __shfl_xor_sync(0xffffffffu, v, 1);
            v += __shfl_xor_sync(0xffffffffu, v, 2);
            if ((lane & 3) == 0) {
                int lrow = warp_m * 32 + mt * 16 + h * 8 + (lane >> 2);
                red[lrow * 2 + warp_n] = v;
            }
        }
    __syncthreads();
    if (tid < MT)
        g_scores[b * NS + s0 + tid] = red[tid * 2] + red[tid * 2 + 1];
}

// ------------------------------------------------------------------
// v_ts + v_ns with inline softmax.  grid (3, 64) = 192 CTAs.
// 512 thr: softmax over 512 scores, then 4 s-quarters x 128 thr x half2
// ------------------------------------------------------------------
__global__ __launch_bounds__(512) void k_vts() {
    int b = blockIdx.y;
    int dc = blockIdx.x;
    int tid = threadIdx.x;
    __shared__ float sw[NS];
    __shared__ float red[512];
    __shared__ float sp[4][128][2];
    float mlen = g_mlen[b];

    float v = g_scores[b * NS + tid];
    red[tid] = v;
    __syncthreads();
    for (int o = 256; o > 0; o >>= 1) {
        if (tid < o) red[tid] = fmaxf(red[tid], red[tid + o]);
        __syncthreads();
    }
    float m = red[0];
    __syncthreads();
    float e = expf(v - m);
    red[tid] = e;
    __syncthreads();
    for (int o = 256; o > 0; o >>= 1) {
        if (tid < o) red[tid] += red[tid + o];
        __syncthreads();
    }
    float inv = 1.0f / red[0];
    float s = (float)tid;
    float l = (s < mlen) ? (1.0f - s / mlen) : 1.0f;
    sw[tid] = e * inv * l;
    __syncthreads();

    int sq = tid >> 7;           // 4 s-quarters of 128
    int dd = tid & 127;          // 128 half2 = 256 d
    int d = dc * 256 + dd * 2;
    const __half2* p = (const __half2*)(g_Ah + ((size_t)b * NS + sq * 128) * ND + d);
    float a0 = 0.f, a1 = 0.f;
#pragma unroll 8
    for (int s2 = 0; s2 < 128; s2++) {
        float2 h = __half22float2(p[(size_t)s2 * (ND / 2)]);
        float w = sw[sq * 128 + s2];
        a0 = fmaf(w, h.x, a0);
        a1 = fmaf(w, h.y, a1);
    }
    sp[sq][dd][0] = a0;
    sp[sq][dd][1] = a1;
    __syncthreads();
    if (sq == 0) {
        float t0 = sp[0][dd][0] + sp[1][dd][0] + sp[2][dd][0] + sp[3][dd][0];
        float t1 = sp[0][dd][1] + sp[1][dd][1] + sp[2][dd][1] + sp[3][dd][1];
        g_vns[b * ND + d] = t0 + g_vs[b * ND + d];
        g_vns[b * ND + d + 1] = t1 + g_vs[b * ND + d + 1];
    }
}

// ------------------------------------------------------------------
// v_ms = tanh(v_ns @ Wm + bm)
// grid (ND/128, NB/2), 512 thr = 128 d x 4 k-quarters; 2 b's/thread
// ------------------------------------------------------------------
__global__ __launch_bounds__(512) void k_vms(const float* __restrict__ Wm,
                                             const float* __restrict__ bm) {
    __shared__ float sp[4][128][2];
    int tid = threadIdx.x;
    int dt = tid & 127;
    int d = blockIdx.x * 128 + dt;
    int q = tid >> 7;
    int b0 = blockIdx.y * 2;
    const float* vb = g_vns + (size_t)b0 * ND;
    int k0 = q * 192;
    float a0 = 0.f, a1 = 0.f;
#pragma unroll 4
    for (int k = 0; k < 192; k++) {
        float w = Wm[(size_t)(k0 + k) * ND + d];
        a0 = fmaf(vb[k0 + k], w, a0);
        a1 = fmaf(vb[ND + k0 + k], w, a1);
    }
    sp[q][dt][0] = a0;
    sp[q][dt][1] = a1;
    __syncthreads();
    if (q == 0) {
        float bb = bm[d];
#pragma unroll
        for (int i = 0; i < 2; i++) {
            float s = sp[0][dt][i] + sp[1][dt][i] + sp[2][dt][i] + sp[3][dt][i] + bb;
            g_vms[(b0 + i) * ND + d] = tanhf(s);
        }
    }
}

// ------------------------------------------------------------------
// logits
// ------------------------------------------------------------------
__global__ void k_logits(const float* __restrict__ Wd,
                         const float* __restrict__ bd,
                         float* __restrict__ out) {
    int t = threadIdx.x;
    if (t >= NB * 3) return;
    int b = t / 3, j = t % 3;
    float acc = bd[j];
    const float* v = g_vms + b * ND;
#pragma unroll 4
    for (int d = 0; d < ND; d++) acc = fmaf(v[d], Wd[d * 3 + j], acc);
    out[b * 3 + j] = acc;
}

// ------------------------------------------------------------------
// launch  (6 kernels; #4 = k_vts -> ncu capture)
// ------------------------------------------------------------------
extern "C" void kernel_launch(void* const* d_in, const int* in_sizes, int n_in,
                              void* d_out, int out_size) {
    (void)in_sizes; (void)n_in; (void)out_size;
    const float* mem  = (const float*)d_in[0];
    const float* asp  = (const float*)d_in[1];
    const int* ids    = (const int*)d_in[2];
    const int* tids   = (const int*)d_in[3];
    const float* W1 = (const float*)d_in[4];
    const float* b1 = (const float*)d_in[5];
    const float* w2 = (const float*)d_in[6];
    const float* Wm = (const float*)d_in[7];
    const float* bm = (const float*)d_in[8];
    const float* Wd = (const float*)d_in[9];
    const float* bd = (const float*)d_in[10];
    float* out = (float*)d_out;

    cudaFuncSetAttribute(k_scores, cudaFuncAttributeMaxDynamicSharedMemorySize, SMEMSZ);

    k_head<<<1024, 512>>>(mem, asp, ids, tids, W1);
    k_ctx<<<dim3(ND / 128, NB / 2), 512>>>(W1, b1);
    k_scores<<<dim3(NS / MT, NB), 256, SMEMSZ>>>(w2);
    k_vts<<<dim3(3, NB), 512>>>();
    k_vms<<<dim3(ND / 128, NB / 2), 512>>>(Wm, bm);
    k_logits<<<1, 256>>>(Wd, bd, out);
}

// round 12
// speedup vs baseline: 1.5950x; 1.0878x over previous
#include <cuda_runtime.h>
#include <cuda_fp16.h>
#include <cstdint>

#define NB 64
#define NS 512
#define NTA 8
#define ND 768

// ------------------------------------------------------------------
// scratch (static __device__; no allocations allowed)
// ------------------------------------------------------------------
__device__ float g_mlen[NB], g_alen[NB];
__device__ float g_va[NB * ND], g_vs[NB * ND], g_ctx[NB * ND];
__device__ float g_scores[NB * NS];
__device__ float g_vns[NB * ND], g_vms[NB * ND];

// fp16 operands
__device__ __half g_Ah[(size_t)NB * NS * ND];
__device__ __half g_Bh[(size_t)ND * ND];   // [n][k] = W1_m[k][n]

// ------------------------------------------------------------------
// PTX helpers (baseline ISA only)
// ------------------------------------------------------------------
__device__ __forceinline__ uint32_t smem_u32(const void* p) {
    uint32_t a;
    asm("{ .reg .u64 t; cvta.to.shared.u64 t, %1; cvt.u32.u64 %0, t; }" : "=r"(a) : "l"(p));
    return a;
}
__device__ __forceinline__ void cp16(uint32_t dst, const void* src) {
    asm volatile("cp.async.cg.shared.global [%0], [%1], 16;" :: "r"(dst), "l"(src));
}
#define CP_COMMIT() asm volatile("cp.async.commit_group;" ::: "memory")
#define CP_WAIT1()  asm volatile("cp.async.wait_group 1;" ::: "memory")
#define CP_WAIT0()  asm volatile("cp.async.wait_group 0;" ::: "memory")

__device__ __forceinline__ void ldsm4(uint32_t& r0, uint32_t& r1, uint32_t& r2, uint32_t& r3,
                                      uint32_t addr) {
    asm volatile("ldmatrix.sync.aligned.m8n8.x4.shared.b16 {%0,%1,%2,%3}, [%4];"
                 : "=r"(r0), "=r"(r1), "=r"(r2), "=r"(r3) : "r"(addr));
}
// fp16-accumulate MMA (2 c-regs, f16x2 each)
__device__ __forceinline__ void mma16816h(uint32_t* c, uint32_t a0, uint32_t a1, uint32_t a2,
                                          uint32_t a3, uint32_t b0, uint32_t b1) {
    asm volatile(
        "mma.sync.aligned.m16n8k16.row.col.f16.f16.f16.f16 "
        "{%0,%1}, {%2,%3,%4,%5}, {%6,%7}, {%0,%1};"
        : "+r"(c[0]), "+r"(c[1])
        : "r"(a0), "r"(a1), "r"(a2), "r"(a3), "r"(b0), "r"(b1));
}
__device__ __forceinline__ uint32_t tanh2_f16(uint32_t x) {
    uint32_t y;
    asm("tanh.approx.f16x2 %0, %1;" : "=r"(y) : "r"(x));
    return y;
}

// ------------------------------------------------------------------
// k_head: fused means+convert / W1_m transpose / global lens
// ------------------------------------------------------------------
__global__ __launch_bounds__(512) void k_head(const float* __restrict__ mem,
                                              const float* __restrict__ asp,
                                              const int* __restrict__ ids,
                                              const int* __restrict__ tids,
                                              const float* __restrict__ W1) {
    int blk = blockIdx.x;
    int tid = threadIdx.x;
    if (blk < 384) {
        int b = blk / 6;
        int db = blk % 6;
        __shared__ float sp[4][128];
        __shared__ float s_ml, s_al;
        float* red = &sp[0][0];
        red[tid] = (ids[b * NS + tid] != 0) ? 1.0f : 0.0f;
        __syncthreads();
        for (int o = 256; o > 0; o >>= 1) {
            if (tid < o) red[tid] += red[tid + o];
            __syncthreads();
        }
        if (tid == 0) {
            s_ml = fmaxf(red[0], 1.0f);
            int a = 0;
#pragma unroll
            for (int t = 0; t < NTA; t++) a += (tids[b * NTA + t] != 0);
            s_al = fmaxf((float)a, 1.0f);
        }
        __syncthreads();
        float mlen = s_ml, alen = s_al;
        __syncthreads();
        int d = db * 128 + (tid & 127);
        int q = tid >> 7;
        float acc = 0.f;
        const float* p = mem + ((size_t)b * NS + q * 128) * ND + d;
        __half* ah = g_Ah + ((size_t)b * NS + q * 128) * ND + d;
#pragma unroll 8
        for (int s = 0; s < 128; s++) {
            float v = p[(size_t)s * ND];
            acc += v;
            ah[(size_t)s * ND] = __float2half_rn(v);
        }
        sp[q][tid & 127] = acc;
        __syncthreads();
        if (q == 0) {
            float tot = sp[0][tid] + sp[1][tid] + sp[2][tid] + sp[3][tid];
            g_vs[b * ND + d] = tot / mlen;
            float a = 0.f;
            const float* ap = asp + ((size_t)b * NTA) * ND + d;
#pragma unroll
            for (int t = 0; t < NTA; t++) a += ap[(size_t)t * ND];
            g_va[b * ND + d] = a / alen;
        }
    } else if (blk < 960) {
        __shared__ float t[32][33];
        int bb = blk - 384;
        int k0 = (bb % 24) * 32, n0 = (bb / 24) * 32;
        int tx = tid & 31, ty = tid >> 5;
        for (int i = ty; i < 32; i += 16)
            t[i][tx] = W1[(size_t)(k0 + i) * ND + n0 + tx];
        __syncthreads();
        for (int i = ty; i < 32; i += 16)
            g_Bh[(size_t)(n0 + i) * ND + k0 + tx] = __float2half_rn(t[tx][i]);
    } else {
        int b = blk - 960;
        __shared__ float red[512];
        red[tid] = (ids[b * NS + tid] != 0) ? 1.0f : 0.0f;
        __syncthreads();
        for (int o = 256; o > 0; o >>= 1) {
            if (tid < o) red[tid] += red[tid + o];
            __syncthreads();
        }
        if (tid == 0) {
            g_mlen[b] = fmaxf(red[0], 1.0f);
            int a = 0;
#pragma unroll
            for (int t = 0; t < NTA; t++) a += (tids[b * NTA + t] != 0);
            g_alen[b] = fmaxf((float)a, 1.0f);
        }
    }
}

// ------------------------------------------------------------------
// ctx = v_a @ W1_a + v_s @ W1_s + b1   [unchanged from R10/R11]
// ------------------------------------------------------------------
__global__ __launch_bounds__(512) void k_ctx(const float* __restrict__ W1,
                                             const float* __restrict__ b1) {
    __shared__ float sp[4][128][2];
    int tid = threadIdx.x;
    int dt = tid & 127;
    int d = blockIdx.x * 128 + dt;
    int q = tid >> 7;
    int b0 = blockIdx.y * 2;
    const float* W = W1 + (size_t)(1 + (q >> 1)) * ND * ND + d;
    const float* vb = ((q >> 1) ? g_vs : g_va) + (size_t)b0 * ND;
    int k0 = (q & 1) * 384;
    float a0 = 0.f, a1 = 0.f;
#pragma unroll 4
    for (int k = 0; k < 384; k++) {
        float w = W[(size_t)(k0 + k) * ND];
        a0 = fmaf(vb[k0 + k], w, a0);
        a1 = fmaf(vb[ND + k0 + k], w, a1);
    }
    sp[q][dt][0] = a0;
    sp[q][dt][1] = a1;
    __syncthreads();
    if (q == 0) {
        float bb = b1[d];
#pragma unroll
        for (int i = 0; i < 2; i++) {
            float s = sp[0][dt][i] + sp[1][dt][i] + sp[2][dt][i] + sp[3][dt][i] + bb;
            g_ctx[(b0 + i) * ND + d] = s;
        }
    }
}

// ------------------------------------------------------------------
// fused scores: fp16-accumulate MMA (promote to f32 every 3 ks)
// 512 thr = 4x4 warp grid. MT=128, NTILE=128, KC=64.
// ------------------------------------------------------------------
#define MT 128
#define NTILE 128
#define KC 64
#define NCHUNKS (ND / NTILE)   // 6
#define KSTEPS (ND / KC)       // 12
#define APAD 144

#define OFF_A 0
#define OFF_B 18432
#define BUFSZ 36864
#define OFF_CTX (2 * BUFSZ)
#define OFF_W2  (OFF_CTX + 3072)
#define OFF_RED (OFF_W2 + 3072)
#define SMEMSZ  (OFF_RED + 2048)

struct ScoreCtx {
    const __half* gA;
    uint32_t sbase;
};

__device__ __forceinline__ void stage_tiles(const ScoreCtx& sc, int nbase, int k0, int buf) {
    int tid = threadIdx.x;
    uint32_t sb = sc.sbase + buf * BUFSZ;
#pragma unroll
    for (int t = 0; t < 2; t++) {
        int i = tid + t * 512;
        int r = i >> 3, c = i & 7;
        uint32_t d = sb + r * APAD + c * 16;
        cp16(d + OFF_A, sc.gA + (size_t)r * ND + k0 + c * 8);
        cp16(d + OFF_B, g_Bh + (size_t)(nbase + r) * ND + k0 + c * 8);
    }
}

__global__ void __launch_bounds__(512, 1) k_scores(const float* __restrict__ w2) {
    extern __shared__ char smem[];
    const int tid = threadIdx.x;
    const int b = blockIdx.y;
    const int s0 = blockIdx.x * MT;
    const int lane = tid & 31, wid = tid >> 5;
    const int warp_m = wid & 3, warp_n = wid >> 2;   // 4 x 4 warps

    float* sctx = (float*)(smem + OFF_CTX);
    float* sw2p = (float*)(smem + OFF_W2);
    for (int i = tid; i < ND; i += 512) {
        sctx[i] = g_ctx[b * ND + i];
        sw2p[i] = w2[i];
    }

    ScoreCtx sc;
    sc.gA = g_Ah + ((size_t)b * NS + s0) * ND;
    sc.sbase = smem_u32(smem);

    const float mlen = g_mlen[b];
    float loc[2][2], rowsum[2][2];
#pragma unroll
    for (int mt = 0; mt < 2; mt++)
#pragma unroll
        for (int h = 0; h < 2; h++) {
            float srow = (float)(s0 + warp_m * 32 + mt * 16 + h * 8 + (lane >> 2));
            loc[mt][h] = (srow < mlen) ? (1.0f - srow / mlen) : 1.0f;
            rowsum[mt][h] = 0.f;
        }

    const int a_row = warp_m * 32 + (lane & 7) + ((lane >> 3) & 1) * 8;
    const int a_halfoff = (lane >> 4) * 16;
    const int b_row = warp_n * 32 + (lane & 7) + (lane >> 4) * 8;
    const int b_halfoff = ((lane >> 3) & 1) * 16;

    __syncthreads();

    stage_tiles(sc, 0, 0, 0);
    CP_COMMIT();

    for (int chunk = 0; chunk < NCHUNKS; chunk++) {
        const int nbase = chunk * NTILE;
        float acc[2][4][4];
        uint32_t acch[2][4][2];
#pragma unroll
        for (int mt = 0; mt < 2; mt++)
#pragma unroll
            for (int nt = 0; nt < 4; nt++) {
#pragma unroll
                for (int j = 0; j < 4; j++) acc[mt][nt][j] = 0.f;
                acch[mt][nt][0] = 0u;
                acch[mt][nt][1] = 0u;
            }

        for (int ks = 0; ks < KSTEPS; ks++) {
            const int buf = ks & 1;
            if (ks + 1 < KSTEPS) {
                stage_tiles(sc, nbase, (ks + 1) * KC, buf ^ 1);
                CP_COMMIT();
                CP_WAIT1();
            } else {
                CP_WAIT0();
            }
            __syncthreads();

            const uint32_t sb = sc.sbase + buf * BUFSZ;
#pragma unroll
            for (int kk = 0; kk < 4; kk++) {
                const int kb = kk * 32;
                uint32_t ar[2][4], br[2][4];
#pragma unroll
                for (int mt = 0; mt < 2; mt++)
                    ldsm4(ar[mt][0], ar[mt][1], ar[mt][2], ar[mt][3],
                          sb + OFF_A + (a_row + mt * 16) * APAD + kb + a_halfoff);
#pragma unroll
                for (int nt2 = 0; nt2 < 2; nt2++)
                    ldsm4(br[nt2][0], br[nt2][1], br[nt2][2], br[nt2][3],
                          sb + OFF_B + (b_row + nt2 * 16) * APAD + kb + b_halfoff);
#pragma unroll
                for (int mt = 0; mt < 2; mt++)
#pragma unroll
                    for (int nt2 = 0; nt2 < 2; nt2++)
#pragma unroll
                        for (int s = 0; s < 2; s++)
                            mma16816h(acch[mt][nt2 * 2 + s], ar[mt][0], ar[mt][1], ar[mt][2],
                                      ar[mt][3], br[nt2][2 * s], br[nt2][2 * s + 1]);
            }
            __syncthreads();

            // promote f16 partials to f32 every 3 ks (K=192 chain)
            if ((ks % 3) == 2) {
#pragma unroll
                for (int mt = 0; mt < 2; mt++)
#pragma unroll
                    for (int nt = 0; nt < 4; nt++) {
                        float2 p0 = __half22float2(*(__half2*)&acch[mt][nt][0]);
                        float2 p1 = __half22float2(*(__half2*)&acch[mt][nt][1]);
                        acc[mt][nt][0] += p0.x;
                        acc[mt][nt][1] += p0.y;
                        acc[mt][nt][2] += p1.x;
                        acc[mt][nt][3] += p1.y;
                        acch[mt][nt][0] = 0u;
                        acch[mt][nt][1] = 0u;
                    }
            }
        }

        if (chunk + 1 < NCHUNKS) {
            stage_tiles(sc, nbase + NTILE, 0, 0);
            CP_COMMIT();
        }

        // epilogue: tanh (f16x2) + dot with w2
#pragma unroll
        for (int mt = 0; mt < 2; mt++) {
#pragma unroll
            for (int nt = 0; nt < 4; nt++) {
                const int c0 = nbase + warp_n * 32 + nt * 8 + (lane & 3) * 2;
                const float2 cx = *(const float2*)&sctx[c0];
                const float2 wv = *(const float2*)&sw2p[c0];
                {
                    float u0 = fmaf(loc[mt][0], acc[mt][nt][0], cx.x);
                    float u1 = fmaf(loc[mt][0], acc[mt][nt][1], cx.y);
                    __half2 hp = __floats2half2_rn(u0, u1);
                    uint32_t th = tanh2_f16(*(uint32_t*)&hp);
                    float2 tf = __half22float2(*(__half2*)&th);
                    rowsum[mt][0] = fmaf(tf.x, wv.x, fmaf(tf.y, wv.y, rowsum[mt][0]));
                }
                {
                    float u2 = fmaf(loc[mt][1], acc[mt][nt][2], cx.x);
                    float u3 = fmaf(loc[mt][1], acc[mt][nt][3], cx.y);
                    __half2 hp = __floats2half2_rn(u2, u3);
                    uint32_t th = tanh2_f16(*(uint32_t*)&hp);
                    float2 tf = __half22float2(*(__half2*)&th);
                    rowsum[mt][1] = fmaf(tf.x, wv.x, fmaf(tf.y, wv.y, rowsum[mt][1]));
                }
            }
        }
    }

    // reduce quad lanes, then across 4 warp_n via smem
    float* red = (float*)(smem + OFF_RED);
#pragma unroll
    for (int mt = 0; mt < 2; mt++)
#pragma unroll
        for (int h = 0; h < 2; h++) {
            float v = rowsum[mt][h];
            v += __shfl_xor_sync(0xffffffffu, v, 1);
            v += __shfl_xor_sync(0xffffffffu, v, 2);
            if ((lane & 3) == 0) {
                int lrow = warp_m * 32 + mt * 16 + h * 8 + (lane >> 2);
                red[lrow * 4 + warp_n] = v;
            }
        }
    __syncthreads();
    if (tid < MT)
        g_scores[b * NS + s0 + tid] =
            (red[tid * 4] + red[tid * 4 + 1]) + (red[tid * 4 + 2] + red[tid * 4 + 3]);
}

// ------------------------------------------------------------------
// v_ts + v_ns with inline softmax.  grid (6, 64) = 384 CTAs.
// 512 thr: softmax over 512 scores, then 8 s-eighths x 64 half2
// ------------------------------------------------------------------
__global__ __launch_bounds__(512) void k_vts() {
    int b = blockIdx.y;
    int dc = blockIdx.x;
    int tid = threadIdx.x;
    __shared__ float sw[NS];
    __shared__ float red[512];
    __shared__ float sp[8][64][2];
    float mlen = g_mlen[b];

    float v = g_scores[b * NS + tid];
    red[tid] = v;
    __syncthreads();
    for (int o = 256; o > 0; o >>= 1) {
        if (tid < o) red[tid] = fmaxf(red[tid], red[tid + o]);
        __syncthreads();
    }
    float m = red[0];
    __syncthreads();
    float e = expf(v - m);
    red[tid] = e;
    __syncthreads();
    for (int o = 256; o > 0; o >>= 1) {
        if (tid < o) red[tid] += red[tid + o];
        __syncthreads();
    }
    float inv = 1.0f / red[0];
    float s = (float)tid;
    float l = (s < mlen) ? (1.0f - s / mlen) : 1.0f;
    sw[tid] = e * inv * l;
    __syncthreads();

    int sq = tid >> 6;           // 8 s-eighths of 64
    int dd = tid & 63;           // 64 half2 = 128 d
    int d = dc * 128 + dd * 2;
    const __half2* p = (const __half2*)(g_Ah + ((size_t)b * NS + sq * 64) * ND + d);
    float a0 = 0.f, a1 = 0.f;
#pragma unroll 8
    for (int s2 = 0; s2 < 64; s2++) {
        float2 h = __half22float2(p[(size_t)s2 * (ND / 2)]);
        float w = sw[sq * 64 + s2];
        a0 = fmaf(w, h.x, a0);
        a1 = fmaf(w, h.y, a1);
    }
    sp[sq][dd][0] = a0;
    sp[sq][dd][1] = a1;
    __syncthreads();
    if (sq == 0) {
        float t0 = 0.f, t1 = 0.f;
#pragma unroll
        for (int i = 0; i < 8; i++) {
            t0 += sp[i][dd][0];
            t1 += sp[i][dd][1];
        }
        g_vns[b * ND + d] = t0 + g_vs[b * ND + d];
        g_vns[b * ND + d + 1] = t1 + g_vs[b * ND + d + 1];
    }
}

// ------------------------------------------------------------------
// v_ms = tanh(v_ns @ Wm + bm)   [unchanged]
// ------------------------------------------------------------------
__global__ __launch_bounds__(512) void k_vms(const float* __restrict__ Wm,
                                             const float* __restrict__ bm) {
    __shared__ float sp[4][128][2];
    int tid = threadIdx.x;
    int dt = tid & 127;
    int d = blockIdx.x * 128 + dt;
    int q = tid >> 7;
    int b0 = blockIdx.y * 2;
    const float* vb = g_vns + (size_t)b0 * ND;
    int k0 = q * 192;
    float a0 = 0.f, a1 = 0.f;
#pragma unroll 4
    for (int k = 0; k < 192; k++) {
        float w = Wm[(size_t)(k0 + k) * ND + d];
        a0 = fmaf(vb[k0 + k], w, a0);
        a1 = fmaf(vb[ND + k0 + k], w, a1);
    }
    sp[q][dt][0] = a0;
    sp[q][dt][1] = a1;
    __syncthreads();
    if (q == 0) {
        float bb = bm[d];
#pragma unroll
        for (int i = 0; i < 2; i++) {
            float s = sp[0][dt][i] + sp[1][dt][i] + sp[2][dt][i] + sp[3][dt][i] + bb;
            g_vms[(b0 + i) * ND + d] = tanhf(s);
        }
    }
}

// ------------------------------------------------------------------
// logits: 64 CTAs (one per b), 256 thr, smem tree reduce
// ------------------------------------------------------------------
__global__ __launch_bounds__(256) void k_logits(const float* __restrict__ Wd,
                                                const float* __restrict__ bd,
                                                float* __restrict__ out) {
    int b = blockIdx.x;
    int tid = threadIdx.x;
    __shared__ float red[256][3];
    float a0 = 0.f, a1 = 0.f, a2 = 0.f;
    const float* v = g_vms + b * ND;
    for (int d = tid; d < ND; d += 256) {
        float vv = v[d];
        a0 = fmaf(vv, Wd[d * 3 + 0], a0);
        a1 = fmaf(vv, Wd[d * 3 + 1], a1);
        a2 = fmaf(vv, Wd[d * 3 + 2], a2);
    }
    red[tid][0] = a0;
    red[tid][1] = a1;
    red[tid][2] = a2;
    __syncthreads();
    for (int o = 128; o > 0; o >>= 1) {
        if (tid < o) {
            red[tid][0] += red[tid + o][0];
            red[tid][1] += red[tid + o][1];
            red[tid][2] += red[tid + o][2];
        }
        __syncthreads();
    }
    if (tid < 3)
        out[b * 3 + tid] = red[0][tid] + bd[tid];
}

// ------------------------------------------------------------------
// launch  (6 kernels; #4 = k_vts -> ncu capture)
// ------------------------------------------------------------------
extern "C" void kernel_launch(void* const* d_in, const int* in_sizes, int n_in,
                              void* d_out, int out_size) {
    (void)in_sizes; (void)n_in; (void)out_size;
    const float* mem  = (const float*)d_in[0];
    const float* asp  = (const float*)d_in[1];
    const int* ids    = (const int*)d_in[2];
    const int* tids   = (const int*)d_in[3];
    const float* W1 = (const float*)d_in[4];
    const float* b1 = (const float*)d_in[5];
    const float* w2 = (const float*)d_in[6];
    const float* Wm = (const float*)d_in[7];
    const float* bm = (const float*)d_in[8];
    const float* Wd = (const float*)d_in[9];
    const float* bd = (const float*)d_in[10];
    float* out = (float*)d_out;

    cudaFuncSetAttribute(k_scores, cudaFuncAttributeMaxDynamicSharedMemorySize, SMEMSZ);

    k_head<<<1024, 512>>>(mem, asp, ids, tids, W1);
    k_ctx<<<dim3(ND / 128, NB / 2), 512>>>(W1, b1);
    k_scores<<<dim3(NS / MT, NB), 512, SMEMSZ>>>(w2);
    k_vts<<<dim3(6, NB), 512>>>();
    k_vms<<<dim3(ND / 128, NB / 2), 512>>>(Wm, bm);
    k_logits<<<NB, 256>>>(Wd, bd, out);
}